// round 13
// baseline (speedup 1.0000x reference)
#include <cuda_runtime.h>
#include <cuda_bf16.h>
#include <math.h>
#include <stdint.h>

// ---------------- problem constants ----------------
#define Bb 64
#define Nn 300
#define Cc 256
#define Hh 8
#define HD 32
#define BH (Bb*Hh)          // 512
#define ROWS (Bb*Nn)        // 19200
#define QR 4                // queries per warp (attention)
#define AW 8                // warps in attention CTA (2 CTAs/SM)
#define KP 33               // float pitch for K rows (conflict-free)

// ---------------- scratch (device globals; no runtime alloc) ----------------
__device__ float g_q[BH * Nn * HD];     // [b,h,n,d]
__device__ float g_k[BH * Nn * HD];
__device__ float g_v[BH * Nn * HD];
__device__ float g_posmx[Hh * Nn];      // per-(h,n) positional logit max
__device__ float g_posinv[Hh * Nn];     // g(h) / sum(exp(logit - max))
// bf16 hi/lo decompositions for tensor-core GEMMs
__device__ __align__(16) __nv_bfloat16 g_xhi[ROWS * Cc],  g_xlo[ROWS * Cc];
__device__ __align__(16) __nv_bfloat16 g_whi[768 * Cc],   g_wlo[768 * Cc];   // [Wqk;Wv]
__device__ __align__(16) __nv_bfloat16 g_pwhi[Cc * Cc],   g_pwlo[Cc * Cc];   // Wproj
__device__ __align__(16) __nv_bfloat16 g_ohhi[ROWS * Cc], g_ohlo[ROWS * Cc]; // attn out

// ---------------- packed f32x2 helpers (attention) ----------------
__device__ __forceinline__ unsigned long long pk2(float x, float y) {
    unsigned long long r;
    asm("mov.b64 %0, {%1,%2};" : "=l"(r)
        : "r"(__float_as_uint(x)), "r"(__float_as_uint(y)));
    return r;
}
__device__ __forceinline__ void fma2(unsigned long long& d,
                                     unsigned long long a, unsigned long long b) {
    asm("fma.rn.f32x2 %0, %1, %2, %0;" : "+l"(d) : "l"(a), "l"(b));
}
__device__ __forceinline__ void upk2(float& lo, float& hi, unsigned long long v) {
    uint32_t l, h;
    asm("mov.b64 {%0,%1}, %2;" : "=r"(l), "=r"(h) : "l"(v));
    lo = __uint_as_float(l); hi = __uint_as_float(h);
}

// ---------------- tensor-core helpers (baseline PTX) ----------------
__device__ __forceinline__ void mma16816(float* c, const uint32_t* a, const uint32_t* b) {
    asm volatile("mma.sync.aligned.m16n8k16.row.col.f32.bf16.bf16.f32 "
        "{%0,%1,%2,%3}, {%4,%5,%6,%7}, {%8,%9}, {%0,%1,%2,%3};"
        : "+f"(c[0]), "+f"(c[1]), "+f"(c[2]), "+f"(c[3])
        : "r"(a[0]), "r"(a[1]), "r"(a[2]), "r"(a[3]), "r"(b[0]), "r"(b[1]));
}
#define LDSM4(R, A) \
    asm volatile("ldmatrix.sync.aligned.m8n8.x4.shared.b16 {%0,%1,%2,%3}, [%4];" \
        : "=r"((R)[0]), "=r"((R)[1]), "=r"((R)[2]), "=r"((R)[3]) : "r"(A))

// =====================================================================
// fp32 -> bf16 hi/lo converters
// =====================================================================
__device__ __forceinline__ void cvt_store4(float4 v, __nv_bfloat16* hi, __nv_bfloat16* lo,
                                           size_t e) {
    __nv_bfloat16 h0 = __float2bfloat16(v.x), h1 = __float2bfloat16(v.y);
    __nv_bfloat16 h2 = __float2bfloat16(v.z), h3 = __float2bfloat16(v.w);
    __nv_bfloat16 l0 = __float2bfloat16(v.x - __bfloat162float(h0));
    __nv_bfloat16 l1 = __float2bfloat16(v.y - __bfloat162float(h1));
    __nv_bfloat16 l2 = __float2bfloat16(v.z - __bfloat162float(h2));
    __nv_bfloat16 l3 = __float2bfloat16(v.w - __bfloat162float(h3));
    __nv_bfloat162* hp = (__nv_bfloat162*)(hi + e);
    __nv_bfloat162* lp = (__nv_bfloat162*)(lo + e);
    hp[0] = __halves2bfloat162(h0, h1); hp[1] = __halves2bfloat162(h2, h3);
    lp[0] = __halves2bfloat162(l0, l1); lp[1] = __halves2bfloat162(l2, l3);
}

__global__ void cvt_x_kernel(const float* __restrict__ src, int n4) {
    int i = blockIdx.x * blockDim.x + threadIdx.x;
    if (i >= n4) return;
    cvt_store4(((const float4*)src)[i], g_xhi, g_xlo, (size_t)i * 4);
}

__global__ void cvt_w_kernel(const float* __restrict__ Wqk, const float* __restrict__ Wv,
                             const float* __restrict__ Wproj) {
    int i = blockIdx.x * blockDim.x + threadIdx.x;   // float4 index
    if (i < 49152) {
        size_t e = (size_t)i * 4;
        const float* s = (e < 512u*256u) ? (Wqk + e) : (Wv + e - 512u*256u);
        cvt_store4(*(const float4*)s, g_whi, g_wlo, e);
    } else if (i < 49152 + 16384) {
        size_t e = (size_t)(i - 49152) * 4;
        cvt_store4(((const float4*)Wproj)[i - 49152], g_pwhi, g_pwlo, e);
    }
}

// =====================================================================
// positional softmax stats
// =====================================================================
__global__ void pos_kernel(const float* __restrict__ Wpos,
                           const float* __restrict__ bpos,
                           const float* __restrict__ gating)
{
    int row  = blockIdx.x * 4 + (threadIdx.x >> 5);
    int lane = threadIdx.x & 31;
    if (row >= Hh * Nn) return;
    int h = row / Nn, n = row % Nn;
    float w0 = Wpos[h*3+0], w2 = Wpos[h*3+2], b = bpos[h];

    float s[10], mx = -1e30f;
    #pragma unroll
    for (int t = 0; t < 10; t++) {
        int m = t*32 + lane;
        float v = -1e30f;
        if (m < Nn) { float d = (float)(m - n); v = fmaf(w2*d, d, fmaf(w0, d, b)); }
        s[t] = v; mx = fmaxf(mx, v);
    }
    #pragma unroll
    for (int o = 16; o; o >>= 1) mx = fmaxf(mx, __shfl_xor_sync(0xffffffffu, mx, o));
    float esum = 0.f;
    #pragma unroll
    for (int t = 0; t < 10; t++) esum += __expf(s[t] - mx);
    #pragma unroll
    for (int o = 16; o; o >>= 1) esum += __shfl_xor_sync(0xffffffffu, esum, o);
    if (lane == 0) {
        float g = 1.0f / (1.0f + __expf(-gating[h]));
        g_posmx[row]  = mx;
        g_posinv[row] = g / esum;
    }
}

// =====================================================================
// mma.sync GEMM v2: 512 threads, 32x32 per warp, ldmatrix fragments.
// D[128,128] tile of A[rows,256] @ W[ncols,256]^T,
// 3-term bf16 split (fp32 accum). K chunked by 32, register prefetch.
// mode 0: A=g_xhi/lo, W=g_whi/lo -> scatter q/k/v. mode 1: out=D+bias.
// =====================================================================
#define PAD 40                       // bf16 elems per row (80 B)
#define TILE_B (128 * PAD * 2)       // 10240 B per tile

__global__ __launch_bounds__(512, 2)
void tc_gemm(const float* __restrict__ bias, float* __restrict__ out, int mode)
{
    __shared__ __align__(16) __nv_bfloat16 sm[4][128 * PAD];   // Ahi,Alo,Bhi,Blo

    int tid = threadIdx.x, wid = tid >> 5, lane = tid & 31;
    int row0 = blockIdx.y * 128;
    int col0 = blockIdx.x * 128;
    int warpM = wid & 3;             // 4 x 32 rows
    int warpN = wid >> 2;            // 4 x 32 cols

    const __nv_bfloat16* srcs[4];
    if (mode == 0) {
        srcs[0] = g_xhi + (size_t)row0 * 256;
        srcs[1] = g_xlo + (size_t)row0 * 256;
        srcs[2] = g_whi + (size_t)col0 * 256;
        srcs[3] = g_wlo + (size_t)col0 * 256;
    } else {
        srcs[0] = g_ohhi + (size_t)row0 * 256;
        srcs[1] = g_ohlo + (size_t)row0 * 256;
        srcs[2] = g_pwhi + (size_t)col0 * 256;
        srcs[3] = g_pwlo + (size_t)col0 * 256;
    }

    uint32_t sb0 = (uint32_t)__cvta_generic_to_shared(&sm[0][0]);

    // loader: one uint4 per tile per thread; r = tid>>2, u = tid&3
    int lr = tid >> 2, lu = tid & 3;

    // ldmatrix per-lane address components
    int a_row = ((lane >> 3) & 1) * 8 + (lane & 7);   // + warpM*32 + mt*16
    int a_k   = (lane >> 4) * 16;                      // + kg*32
    int b_row = ((lane >> 4) & 1) * 8 + (lane & 7);   // + warpN*32 + ntp*16
    int b_k   = ((lane >> 3) & 1) * 16;                // + kg*32

    float acc[2][4][4];
    #pragma unroll
    for (int mt = 0; mt < 2; mt++)
        #pragma unroll
        for (int nt = 0; nt < 4; nt++)
            #pragma unroll
            for (int f = 0; f < 4; f++) acc[mt][nt][f] = 0.f;

    uint4 rv[4];
    #pragma unroll
    for (int t = 0; t < 4; t++)
        rv[t] = *(const uint4*)(srcs[t] + (size_t)lr * 256 + lu * 8);
    #pragma unroll
    for (int t = 0; t < 4; t++)
        *(uint4*)((char*)sm[t] + lr * (PAD*2) + lu * 16) = rv[t];

    for (int kc = 0; kc < 8; kc++) {
        __syncthreads();
        if (kc < 7) {
            int k0 = (kc + 1) * 32;
            #pragma unroll
            for (int t = 0; t < 4; t++)
                rv[t] = *(const uint4*)(srcs[t] + (size_t)lr * 256 + k0 + lu * 8);
        }

        #pragma unroll
        for (int kg = 0; kg < 2; kg++) {
            int kb = kg * 32;
            uint32_t Ah[2][4], Al[2][4];
            #pragma unroll
            for (int mt = 0; mt < 2; mt++) {
                uint32_t ad = sb0 + (warpM*32 + mt*16 + a_row) * (PAD*2) + a_k + kb;
                LDSM4(Ah[mt], ad);
                LDSM4(Al[mt], ad + TILE_B);
            }
            uint32_t Bh[4][2], Bl[4][2];
            #pragma unroll
            for (int ntp = 0; ntp < 2; ntp++) {
                uint32_t bd = sb0 + 2*TILE_B +
                              (warpN*32 + ntp*16 + b_row) * (PAD*2) + b_k + kb;
                uint32_t rh[4], rl[4];
                LDSM4(rh, bd);
                LDSM4(rl, bd + TILE_B);
                Bh[2*ntp][0]   = rh[0]; Bh[2*ntp][1]   = rh[1];
                Bh[2*ntp+1][0] = rh[2]; Bh[2*ntp+1][1] = rh[3];
                Bl[2*ntp][0]   = rl[0]; Bl[2*ntp][1]   = rl[1];
                Bl[2*ntp+1][0] = rl[2]; Bl[2*ntp+1][1] = rl[3];
            }
            #pragma unroll
            for (int mt = 0; mt < 2; mt++)
                #pragma unroll
                for (int nt = 0; nt < 4; nt++) {
                    mma16816(acc[mt][nt], Ah[mt], Bh[nt]);
                    mma16816(acc[mt][nt], Al[mt], Bh[nt]);
                    mma16816(acc[mt][nt], Ah[mt], Bl[nt]);
                }
        }

        if (kc < 7) {
            __syncthreads();
            #pragma unroll
            for (int t = 0; t < 4; t++)
                *(uint4*)((char*)sm[t] + lr * (PAD*2) + lu * 16) = rv[t];
        }
    }

    // ---------------- epilogue ----------------
    int colbase = col0 + warpN * 32;
    int sec = colbase >> 8;                       // mode0: 0=q 1=k 2=v
    int h   = (colbase >> 5) & 7;
    #pragma unroll
    for (int mt = 0; mt < 2; mt++) {
        #pragma unroll
        for (int rr = 0; rr < 2; rr++) {
            int r = row0 + warpM*32 + mt*16 + (lane >> 2) + rr*8;
            int bidx = r / Nn, n = r % Nn;
            #pragma unroll
            for (int nt = 0; nt < 4; nt++) {
                int d = nt*8 + (lane & 3)*2;
                float d0 = acc[mt][nt][rr*2 + 0];
                float d1 = acc[mt][nt][rr*2 + 1];
                if (mode == 0) {
                    float* basep = (sec == 0) ? g_q : (sec == 1) ? g_k : g_v;
                    *(float2*)(basep + (((size_t)bidx*Hh + h)*Nn + n)*HD + d) =
                        make_float2(d0, d1);
                } else {
                    int col = colbase + d;
                    *(float2*)(out + (size_t)r * 256 + col) =
                        make_float2(d0 + bias[col], d1 + bias[col + 1]);
                }
            }
        }
    }
}

// =====================================================================
// Attention (R9/R12 measured-best): one CTA per (b,h), 8 warps, QR=4,
// 2 CTAs/SM. Output stored as bf16 hi/lo for the tensor-core proj.
// =====================================================================
#define SM_U64_VS2 ((Nn/2)*32)                 // 4800 u64
#define SM_F_KS    (Nn*KP)                     // 9900 f
#define ATTN_SMEM_BYTES (SM_U64_VS2*8 + (SM_F_KS + AW*32*QR + AW*QR*32)*4)

__global__ __launch_bounds__(AW*32, 2)
void attn_kernel(const float* __restrict__ Wpos,
                 const float* __restrict__ bpos,
                 const float* __restrict__ gating)
{
    extern __shared__ __align__(16) unsigned long long smu[];
    unsigned long long* vs2 = smu;                         // (V[m],V[m+1])
    float* ks  = (float*)(smu + SM_U64_VS2);               // [m*KP + d]
    float* qs  = ks + SM_F_KS;
    float* scb = qs + AW*32*QR;

    int bh = blockIdx.x;
    int h  = bh & 7, bidx = bh >> 3;
    int tid = threadIdx.x, wid = tid >> 5, lane = tid & 31;

    const float* kg = g_k + (size_t)bh * Nn * HD;
    const float* vg = g_v + (size_t)bh * Nn * HD;
    const float* qg = g_q + (size_t)bh * Nn * HD;

    for (int i = tid; i < Nn * 8; i += AW*32) {
        int m = i >> 3, d = (i & 7) * 4;
        float4 kv4 = *(const float4*)(kg + m*HD + d);
        ks[m*KP + d + 0] = kv4.x; ks[m*KP + d + 1] = kv4.y;
        ks[m*KP + d + 2] = kv4.z; ks[m*KP + d + 3] = kv4.w;
    }
    for (int i = tid; i < (Nn/2) * 8; i += AW*32) {
        int mp = i >> 3, d = (i & 7) * 4;
        float4 va = *(const float4*)(vg + (2*mp)*HD + d);
        float4 vb = *(const float4*)(vg + (2*mp+1)*HD + d);
        vs2[mp*32 + d + 0] = pk2(va.x, vb.x);
        vs2[mp*32 + d + 1] = pk2(va.y, vb.y);
        vs2[mp*32 + d + 2] = pk2(va.z, vb.z);
        vs2[mp*32 + d + 3] = pk2(va.w, vb.w);
    }
    __syncthreads();

    float g  = 1.0f / (1.0f + __expf(-gating[h]));
    float w0 = Wpos[h*3+0], w2 = Wpos[h*3+2], bps = bpos[h];
    const float scale = 0.17677669529663687f;
    float* myq  = qs  + wid * (32*QR);
    float* mysc = scb + wid * (QR*32);

    for (int n0 = wid*QR; n0 < Nn; n0 += AW*QR) {
        {
            float q0 = qg[(n0+0)*HD + lane];
            float q1 = qg[(n0+1)*HD + lane];
            float q2 = qg[(n0+2)*HD + lane];
            float q3 = qg[(n0+3)*HD + lane];
            *(float4*)&myq[lane*QR] = make_float4(q0, q1, q2, q3);
        }
        __syncwarp();

        unsigned long long acc2[2][10];
        #pragma unroll
        for (int p = 0; p < 2; p++)
            #pragma unroll
            for (int t = 0; t < 10; t++) acc2[p][t] = 0ULL;

        #pragma unroll
        for (int d = 0; d < HD; d++) {
            ulonglong2 qp = *(const ulonglong2*)&myq[d*QR];
            #pragma unroll
            for (int t = 0; t < 10; t++) {
                float kv = ks[(t*32 + lane)*KP + d];
                unsigned long long kp = pk2(kv, kv);
                fma2(acc2[0][t], qp.x, kp);
                fma2(acc2[1][t], qp.y, kp);
            }
        }

        float s[QR][10], inv[QR], pmx[QR], pw[QR];
        #pragma unroll
        for (int qq = 0; qq < QR; qq++) {
            int n = n0 + qq;
            float mx = -1e30f;
            #pragma unroll
            for (int t = 0; t < 10; t++) {
                float lo, hi; upk2(lo, hi, acc2[qq >> 1][t]);
                float v = (qq & 1) ? hi : lo;
                int m = t*32 + lane;
                v = (m < Nn) ? v * scale : -1e30f;
                s[qq][t] = v; mx = fmaxf(mx, v);
            }
            #pragma unroll
            for (int o = 16; o; o >>= 1) mx = fmaxf(mx, __shfl_xor_sync(0xffffffffu, mx, o));
            float esum = 0.f;
            #pragma unroll
            for (int t = 0; t < 10; t++) { s[qq][t] = __expf(s[qq][t] - mx); esum += s[qq][t]; }
            #pragma unroll
            for (int o = 16; o; o >>= 1) esum += __shfl_xor_sync(0xffffffffu, esum, o);
            inv[qq] = (1.0f - g) / esum;
            pmx[qq] = g_posmx[h*Nn + n];
            pw[qq]  = g_posinv[h*Nn + n];
        }

        unsigned long long o2[QR];
        #pragma unroll
        for (int qq = 0; qq < QR; qq++) o2[qq] = 0ULL;

        #pragma unroll
        for (int t = 0; t < 10; t++) {
            int m = t*32 + lane;
            float fm = (float)m;
            #pragma unroll
            for (int qq = 0; qq < QR; qq++) {
                float av = 0.f;
                if (m < Nn) {
                    float dd = fm - (float)(n0 + qq);
                    float pe = __expf(fmaf(w2*dd, dd, fmaf(w0, dd, bps)) - pmx[qq]) * pw[qq];
                    av = fmaf(s[qq][t], inv[qq], pe);
                }
                mysc[qq*32 + lane] = av;
            }
            __syncwarp();
            int j4max = (t < 9) ? 8 : 3;
            for (int j4 = 0; j4 < j4max; j4++) {
                unsigned long long vp0 = vs2[(t*16 + 2*j4 + 0)*32 + lane];
                unsigned long long vp1 = vs2[(t*16 + 2*j4 + 1)*32 + lane];
                #pragma unroll
                for (int qq = 0; qq < QR; qq++) {
                    ulonglong2 a4 = *(const ulonglong2*)&mysc[qq*32 + j4*4];
                    fma2(o2[qq], a4.x, vp0);
                    fma2(o2[qq], a4.y, vp1);
                }
            }
            __syncwarp();
        }

        #pragma unroll
        for (int qq = 0; qq < QR; qq++) {
            float lo, hi; upk2(lo, hi, o2[qq]);
            float val = lo + hi;
            __nv_bfloat16 hb = __float2bfloat16(val);
            __nv_bfloat16 lb = __float2bfloat16(val - __bfloat162float(hb));
            size_t idx = ((size_t)bidx*Nn + (n0+qq))*Cc + h*HD + lane;
            g_ohhi[idx] = hb;
            g_ohlo[idx] = lb;
        }
    }
}

// =====================================================================
extern "C" void kernel_launch(void* const* d_in, const int* in_sizes, int n_in,
                              void* d_out, int out_size)
{
    const float* x      = (const float*)d_in[0];
    const float* Wqk    = (const float*)d_in[1];
    const float* Wv     = (const float*)d_in[2];
    const float* Wpos   = (const float*)d_in[3];
    const float* bpos   = (const float*)d_in[4];
    const float* Wproj  = (const float*)d_in[5];
    const float* bproj  = (const float*)d_in[6];
    const float* gating = (const float*)d_in[7];
    float* out = (float*)d_out;

    cudaFuncSetAttribute(attn_kernel, cudaFuncAttributeMaxDynamicSharedMemorySize,
                         ATTN_SMEM_BYTES);

    // 0) bf16 hi/lo conversions
    int n4x = ROWS * Cc / 4;
    cvt_x_kernel<<<(n4x + 255) / 256, 256>>>(x, n4x);
    cvt_w_kernel<<<(49152 + 16384 + 255) / 256, 256>>>(Wqk, Wv, Wproj);

    // 1) positional softmax stats
    pos_kernel<<<(Hh*Nn + 3) / 4, 128>>>(Wpos, bpos, gating);

    // 2) QKV projection on tensor cores: [19200,256] @ [768,256]^T
    dim3 g1(6, ROWS / 128);
    tc_gemm<<<g1, 512>>>(nullptr, nullptr, 0);

    // 3) fused gated attention, one CTA per (b,h)
    attn_kernel<<<BH, AW*32, ATTN_SMEM_BYTES>>>(Wpos, bpos, gating);

    // 4) output projection on tensor cores + bias
    dim3 g2(2, ROWS / 128);
    tc_gemm<<<g2, 512>>>(bproj, out, 1);
}

// round 14
// speedup vs baseline: 1.0205x; 1.0205x over previous
#include <cuda_runtime.h>
#include <cuda_bf16.h>
#include <math.h>
#include <stdint.h>

// ---------------- problem constants ----------------
#define Bb 64
#define Nn 300
#define Cc 256
#define Hh 8
#define HD 32
#define BH (Bb*Hh)          // 512
#define ROWS (Bb*Nn)        // 19200
#define QR 4                // queries per warp (attention)
#define AW 8                // warps in attention CTA (2 CTAs/SM)
#define KP 33               // float pitch for K rows (conflict-free)

// ---------------- scratch (device globals; no runtime alloc) ----------------
__device__ float g_q[BH * Nn * HD];     // [b,h,n,d]
__device__ float g_k[BH * Nn * HD];
__device__ float g_v[BH * Nn * HD];
__device__ float g_pos[Hh * Nn * Nn];   // g * softmax(pos logits), 2.9MB -> L2
// bf16 hi/lo decompositions for tensor-core GEMMs
__device__ __align__(16) __nv_bfloat16 g_xhi[ROWS * Cc],  g_xlo[ROWS * Cc];
__device__ __align__(16) __nv_bfloat16 g_whi[768 * Cc],   g_wlo[768 * Cc];   // [Wqk;Wv]
__device__ __align__(16) __nv_bfloat16 g_pwhi[Cc * Cc],   g_pwlo[Cc * Cc];   // Wproj
__device__ __align__(16) __nv_bfloat16 g_ohhi[ROWS * Cc], g_ohlo[ROWS * Cc]; // attn out

// ---------------- packed f32x2 helpers (attention) ----------------
__device__ __forceinline__ unsigned long long pk2(float x, float y) {
    unsigned long long r;
    asm("mov.b64 %0, {%1,%2};" : "=l"(r)
        : "r"(__float_as_uint(x)), "r"(__float_as_uint(y)));
    return r;
}
__device__ __forceinline__ void fma2(unsigned long long& d,
                                     unsigned long long a, unsigned long long b) {
    asm("fma.rn.f32x2 %0, %1, %2, %0;" : "+l"(d) : "l"(a), "l"(b));
}
__device__ __forceinline__ void upk2(float& lo, float& hi, unsigned long long v) {
    uint32_t l, h;
    asm("mov.b64 {%0,%1}, %2;" : "=r"(l), "=r"(h) : "l"(v));
    lo = __uint_as_float(l); hi = __uint_as_float(h);
}

// ---------------- mma.sync helper (baseline PTX, sm_80+) ----------------
__device__ __forceinline__ void mma16816(float* c, const uint32_t* a, const uint32_t* b) {
    asm volatile("mma.sync.aligned.m16n8k16.row.col.f32.bf16.bf16.f32 "
        "{%0,%1,%2,%3}, {%4,%5,%6,%7}, {%8,%9}, {%0,%1,%2,%3};"
        : "+f"(c[0]), "+f"(c[1]), "+f"(c[2]), "+f"(c[3])
        : "r"(a[0]), "r"(a[1]), "r"(a[2]), "r"(a[3]), "r"(b[0]), "r"(b[1]));
}

// =====================================================================
// fp32 -> bf16 hi/lo converters
// =====================================================================
__device__ __forceinline__ void cvt_store4(float4 v, __nv_bfloat16* hi, __nv_bfloat16* lo,
                                           size_t e) {
    __nv_bfloat16 h0 = __float2bfloat16(v.x), h1 = __float2bfloat16(v.y);
    __nv_bfloat16 h2 = __float2bfloat16(v.z), h3 = __float2bfloat16(v.w);
    __nv_bfloat16 l0 = __float2bfloat16(v.x - __bfloat162float(h0));
    __nv_bfloat16 l1 = __float2bfloat16(v.y - __bfloat162float(h1));
    __nv_bfloat16 l2 = __float2bfloat16(v.z - __bfloat162float(h2));
    __nv_bfloat16 l3 = __float2bfloat16(v.w - __bfloat162float(h3));
    __nv_bfloat162* hp = (__nv_bfloat162*)(hi + e);
    __nv_bfloat162* lp = (__nv_bfloat162*)(lo + e);
    hp[0] = __halves2bfloat162(h0, h1); hp[1] = __halves2bfloat162(h2, h3);
    lp[0] = __halves2bfloat162(l0, l1); lp[1] = __halves2bfloat162(l2, l3);
}

__global__ void cvt_x_kernel(const float* __restrict__ src, int n4) {
    int i = blockIdx.x * blockDim.x + threadIdx.x;
    if (i >= n4) return;
    cvt_store4(((const float4*)src)[i], g_xhi, g_xlo, (size_t)i * 4);
}

__global__ void cvt_w_kernel(const float* __restrict__ Wqk, const float* __restrict__ Wv,
                             const float* __restrict__ Wproj) {
    int i = blockIdx.x * blockDim.x + threadIdx.x;   // float4 index
    if (i < 49152) {
        size_t e = (size_t)i * 4;
        const float* s = (e < 512u*256u) ? (Wqk + e) : (Wv + e - 512u*256u);
        cvt_store4(*(const float4*)s, g_whi, g_wlo, e);
    } else if (i < 49152 + 16384) {
        size_t e = (size_t)(i - 49152) * 4;
        cvt_store4(((const float4*)Wproj)[i - 49152], g_pwhi, g_pwlo, e);
    }
}

// =====================================================================
// positional softmax, full precompute scaled by gate:
// g_pos[h][n][m] = sigmoid(gating[h]) * softmax_m(w0*d + w2*d^2 + b)
// Only 8*300*300 values — shared by all 64 batches.
// =====================================================================
__global__ void pos_kernel(const float* __restrict__ Wpos,
                           const float* __restrict__ bpos,
                           const float* __restrict__ gating)
{
    int row  = blockIdx.x * 4 + (threadIdx.x >> 5);   // h*300 + n
    int lane = threadIdx.x & 31;
    if (row >= Hh * Nn) return;
    int h = row / Nn, n = row % Nn;
    float w0 = Wpos[h*3+0], w2 = Wpos[h*3+2], b = bpos[h];

    float s[10], mx = -1e30f;
    #pragma unroll
    for (int t = 0; t < 10; t++) {
        int m = t*32 + lane;
        float v = -1e30f;
        if (m < Nn) { float d = (float)(m - n); v = fmaf(w2*d, d, fmaf(w0, d, b)); }
        s[t] = v; mx = fmaxf(mx, v);
    }
    #pragma unroll
    for (int o = 16; o; o >>= 1) mx = fmaxf(mx, __shfl_xor_sync(0xffffffffu, mx, o));
    float esum = 0.f;
    #pragma unroll
    for (int t = 0; t < 10; t++) { s[t] = __expf(s[t] - mx); esum += s[t]; }
    #pragma unroll
    for (int o = 16; o; o >>= 1) esum += __shfl_xor_sync(0xffffffffu, esum, o);
    float g = 1.0f / (1.0f + __expf(-gating[h]));
    float inv = g / esum;
    float* dst = g_pos + (size_t)row * Nn;
    #pragma unroll
    for (int t = 0; t < 10; t++) {
        int m = t*32 + lane;
        if (m < Nn) dst[m] = s[t] * inv;
    }
}

// =====================================================================
// mma.sync GEMM (R12 measured-best): 256 threads, 64x32 per warp,
// plain LDS fragment loads. D[128,128] tile of A[rows,256] @ W[n,256]^T,
// 3-term bf16 split (fp32 accum), K chunked by 32, register prefetch.
// mode 0: A=g_xhi/lo, W=g_whi/lo -> scatter q/k/v. mode 1: out=D+bias.
// =====================================================================
#define PAD 40   // row pitch in bf16 elems (80B)

__global__ __launch_bounds__(256, 2)
void tc_gemm(const float* __restrict__ bias, float* __restrict__ out, int mode)
{
    __shared__ __align__(16) __nv_bfloat16 sm[4][128 * PAD];   // Ahi,Alo,Bhi,Blo

    int tid = threadIdx.x, wid = tid >> 5, lane = tid & 31;
    int row0 = blockIdx.y * 128;
    int col0 = blockIdx.x * 128;
    int warpM = wid & 1;           // 2 x 64 rows
    int warpN = wid >> 1;          // 4 x 32 cols
    int g  = lane >> 2;            // fragment row group 0..7
    int tg = lane & 3;             // fragment k group

    const __nv_bfloat16* srcs[4];
    if (mode == 0) {
        srcs[0] = g_xhi + (size_t)row0 * 256;
        srcs[1] = g_xlo + (size_t)row0 * 256;
        srcs[2] = g_whi + (size_t)col0 * 256;
        srcs[3] = g_wlo + (size_t)col0 * 256;
    } else {
        srcs[0] = g_ohhi + (size_t)row0 * 256;
        srcs[1] = g_ohlo + (size_t)row0 * 256;
        srcs[2] = g_pwhi + (size_t)col0 * 256;
        srcs[3] = g_pwlo + (size_t)col0 * 256;
    }

    int lr_half = tid >> 2;        // 0..63
    int lu = tid & 3;              // 16B unit within 32-elem chunk

    float acc[4][4][4];
    #pragma unroll
    for (int mt = 0; mt < 4; mt++)
        #pragma unroll
        for (int nt = 0; nt < 4; nt++)
            #pragma unroll
            for (int f = 0; f < 4; f++) acc[mt][nt][f] = 0.f;

    uint4 rv[8];
    #pragma unroll
    for (int i = 0; i < 8; i++) {
        int tile = i >> 1;
        int r = (i & 1) * 64 + lr_half;
        rv[i] = *(const uint4*)(srcs[tile] + (size_t)r * 256 + lu * 8);
    }
    #pragma unroll
    for (int i = 0; i < 8; i++) {
        int tile = i >> 1;
        int r = (i & 1) * 64 + lr_half;
        *(uint4*)((char*)sm[tile] + r * (PAD*2) + lu * 16) = rv[i];
    }

    for (int kc = 0; kc < 8; kc++) {
        __syncthreads();
        if (kc < 7) {
            int k0 = (kc + 1) * 32;
            #pragma unroll
            for (int i = 0; i < 8; i++) {
                int tile = i >> 1;
                int r = (i & 1) * 64 + lr_half;
                rv[i] = *(const uint4*)(srcs[tile] + (size_t)r * 256 + k0 + lu * 8);
            }
        }

        #pragma unroll
        for (int kg = 0; kg < 2; kg++) {
            int kb = kg * 16 + tg * 2;        // element offset in row
            uint32_t Ah[4][4], Al[4][4];
            #pragma unroll
            for (int mt = 0; mt < 4; mt++) {
                const char* pa = (const char*)sm[0] +
                                 (warpM*64 + mt*16 + g) * (PAD*2) + kb * 2;
                const char* pl = (const char*)sm[1] +
                                 (warpM*64 + mt*16 + g) * (PAD*2) + kb * 2;
                Ah[mt][0] = *(const uint32_t*)(pa);
                Ah[mt][1] = *(const uint32_t*)(pa + 8 * (PAD*2));
                Ah[mt][2] = *(const uint32_t*)(pa + 16);
                Ah[mt][3] = *(const uint32_t*)(pa + 8 * (PAD*2) + 16);
                Al[mt][0] = *(const uint32_t*)(pl);
                Al[mt][1] = *(const uint32_t*)(pl + 8 * (PAD*2));
                Al[mt][2] = *(const uint32_t*)(pl + 16);
                Al[mt][3] = *(const uint32_t*)(pl + 8 * (PAD*2) + 16);
            }
            uint32_t Bh[4][2], Bl[4][2];
            #pragma unroll
            for (int nt = 0; nt < 4; nt++) {
                const char* pb = (const char*)sm[2] +
                                 (warpN*32 + nt*8 + g) * (PAD*2) + kb * 2;
                const char* pbl = (const char*)sm[3] +
                                 (warpN*32 + nt*8 + g) * (PAD*2) + kb * 2;
                Bh[nt][0] = *(const uint32_t*)(pb);
                Bh[nt][1] = *(const uint32_t*)(pb + 16);
                Bl[nt][0] = *(const uint32_t*)(pbl);
                Bl[nt][1] = *(const uint32_t*)(pbl + 16);
            }
            #pragma unroll
            for (int mt = 0; mt < 4; mt++)
                #pragma unroll
                for (int nt = 0; nt < 4; nt++) {
                    mma16816(acc[mt][nt], Ah[mt], Bh[nt]);
                    mma16816(acc[mt][nt], Al[mt], Bh[nt]);
                    mma16816(acc[mt][nt], Ah[mt], Bl[nt]);
                }
        }

        if (kc < 7) {
            __syncthreads();
            #pragma unroll
            for (int i = 0; i < 8; i++) {
                int tile = i >> 1;
                int r = (i & 1) * 64 + lr_half;
                *(uint4*)((char*)sm[tile] + r * (PAD*2) + lu * 16) = rv[i];
            }
        }
    }

    // ---------------- epilogue ----------------
    int sec = col0 >> 8;                                  // mode0: 0=q 1=k 2=v
    int h   = ((col0 & 255) >> 5) + warpN;                // one head per warp
    #pragma unroll
    for (int mt = 0; mt < 4; mt++) {
        #pragma unroll
        for (int rr = 0; rr < 2; rr++) {
            int r = row0 + warpM*64 + mt*16 + (lane >> 2) + rr*8;
            int bidx = r / Nn, n = r % Nn;
            #pragma unroll
            for (int nt = 0; nt < 4; nt++) {
                int col = col0 + warpN*32 + nt*8 + (lane & 3)*2;
                float d0 = acc[mt][nt][rr*2 + 0];
                float d1 = acc[mt][nt][rr*2 + 1];
                if (mode == 0) {
                    float* basep = (sec == 0) ? g_q : (sec == 1) ? g_k : g_v;
                    int d = col & 31;
                    *(float2*)(basep + (((size_t)bidx*Hh + h)*Nn + n)*HD + d) =
                        make_float2(d0, d1);
                } else {
                    *(float2*)(out + (size_t)r * 256 + col) =
                        make_float2(d0 + bias[col], d1 + bias[col + 1]);
                }
            }
        }
    }
}

// =====================================================================
// Attention: one CTA per (b,h), 8 warps, QR=4, 2 CTAs/SM.
// Pos weights now READ from the precomputed, gate-scaled g_pos (L2-
// resident, shared across all 64 batches) instead of recomputed with
// exp — halves the attention MUFU load. Output stored bf16 hi/lo.
// =====================================================================
#define SM_U64_VS2 ((Nn/2)*32)                 // 4800 u64
#define SM_F_KS    (Nn*KP)                     // 9900 f
#define ATTN_SMEM_BYTES (SM_U64_VS2*8 + (SM_F_KS + AW*32*QR + AW*QR*32)*4)

__global__ __launch_bounds__(AW*32, 2)
void attn_kernel(const float* __restrict__ gating)
{
    extern __shared__ __align__(16) unsigned long long smu[];
    unsigned long long* vs2 = smu;                         // (V[m],V[m+1])
    float* ks  = (float*)(smu + SM_U64_VS2);               // [m*KP + d]
    float* qs  = ks + SM_F_KS;
    float* scb = qs + AW*32*QR;

    int bh = blockIdx.x;
    int h  = bh & 7, bidx = bh >> 3;
    int tid = threadIdx.x, wid = tid >> 5, lane = tid & 31;

    const float* kg = g_k + (size_t)bh * Nn * HD;
    const float* vg = g_v + (size_t)bh * Nn * HD;
    const float* qg = g_q + (size_t)bh * Nn * HD;

    for (int i = tid; i < Nn * 8; i += AW*32) {
        int m = i >> 3, d = (i & 7) * 4;
        float4 kv4 = *(const float4*)(kg + m*HD + d);
        ks[m*KP + d + 0] = kv4.x; ks[m*KP + d + 1] = kv4.y;
        ks[m*KP + d + 2] = kv4.z; ks[m*KP + d + 3] = kv4.w;
    }
    for (int i = tid; i < (Nn/2) * 8; i += AW*32) {
        int mp = i >> 3, d = (i & 7) * 4;
        float4 va = *(const float4*)(vg + (2*mp)*HD + d);
        float4 vb = *(const float4*)(vg + (2*mp+1)*HD + d);
        vs2[mp*32 + d + 0] = pk2(va.x, vb.x);
        vs2[mp*32 + d + 1] = pk2(va.y, vb.y);
        vs2[mp*32 + d + 2] = pk2(va.z, vb.z);
        vs2[mp*32 + d + 3] = pk2(va.w, vb.w);
    }
    __syncthreads();

    float g  = 1.0f / (1.0f + __expf(-gating[h]));
    const float scale = 0.17677669529663687f;
    float* myq  = qs  + wid * (32*QR);
    float* mysc = scb + wid * (QR*32);
    const float* posh = g_pos + (size_t)h * Nn * Nn;

    for (int n0 = wid*QR; n0 < Nn; n0 += AW*QR) {
        {
            float q0 = qg[(n0+0)*HD + lane];
            float q1 = qg[(n0+1)*HD + lane];
            float q2 = qg[(n0+2)*HD + lane];
            float q3 = qg[(n0+3)*HD + lane];
            *(float4*)&myq[lane*QR] = make_float4(q0, q1, q2, q3);
        }
        __syncwarp();

        unsigned long long acc2[2][10];
        #pragma unroll
        for (int p = 0; p < 2; p++)
            #pragma unroll
            for (int t = 0; t < 10; t++) acc2[p][t] = 0ULL;

        #pragma unroll
        for (int d = 0; d < HD; d++) {
            ulonglong2 qp = *(const ulonglong2*)&myq[d*QR];
            #pragma unroll
            for (int t = 0; t < 10; t++) {
                float kv = ks[(t*32 + lane)*KP + d];
                unsigned long long kp = pk2(kv, kv);
                fma2(acc2[0][t], qp.x, kp);
                fma2(acc2[1][t], qp.y, kp);
            }
        }

        float s[QR][10], inv[QR];
        #pragma unroll
        for (int qq = 0; qq < QR; qq++) {
            float mx = -1e30f;
            #pragma unroll
            for (int t = 0; t < 10; t++) {
                float lo, hi; upk2(lo, hi, acc2[qq >> 1][t]);
                float v = (qq & 1) ? hi : lo;
                int m = t*32 + lane;
                v = (m < Nn) ? v * scale : -1e30f;
                s[qq][t] = v; mx = fmaxf(mx, v);
            }
            #pragma unroll
            for (int o = 16; o; o >>= 1) mx = fmaxf(mx, __shfl_xor_sync(0xffffffffu, mx, o));
            float esum = 0.f;
            #pragma unroll
            for (int t = 0; t < 10; t++) { s[qq][t] = __expf(s[qq][t] - mx); esum += s[qq][t]; }
            #pragma unroll
            for (int o = 16; o; o >>= 1) esum += __shfl_xor_sync(0xffffffffu, esum, o);
            inv[qq] = (1.0f - g) / esum;
        }

        unsigned long long o2[QR];
        #pragma unroll
        for (int qq = 0; qq < QR; qq++) o2[qq] = 0ULL;

        #pragma unroll
        for (int t = 0; t < 10; t++) {
            int m = t*32 + lane;
            #pragma unroll
            for (int qq = 0; qq < QR; qq++) {
                float av = 0.f;
                if (m < Nn) {
                    float pe = __ldg(posh + (size_t)(n0 + qq) * Nn + m);   // L2 hit
                    av = fmaf(s[qq][t], inv[qq], pe);
                }
                mysc[qq*32 + lane] = av;
            }
            __syncwarp();
            int j4max = (t < 9) ? 8 : 3;
            for (int j4 = 0; j4 < j4max; j4++) {
                unsigned long long vp0 = vs2[(t*16 + 2*j4 + 0)*32 + lane];
                unsigned long long vp1 = vs2[(t*16 + 2*j4 + 1)*32 + lane];
                #pragma unroll
                for (int qq = 0; qq < QR; qq++) {
                    ulonglong2 a4 = *(const ulonglong2*)&mysc[qq*32 + j4*4];
                    fma2(o2[qq], a4.x, vp0);
                    fma2(o2[qq], a4.y, vp1);
                }
            }
            __syncwarp();
        }

        #pragma unroll
        for (int qq = 0; qq < QR; qq++) {
            float lo, hi; upk2(lo, hi, o2[qq]);
            float val = lo + hi;
            __nv_bfloat16 hb = __float2bfloat16(val);
            __nv_bfloat16 lb = __float2bfloat16(val - __bfloat162float(hb));
            size_t idx = ((size_t)bidx*Nn + (n0+qq))*Cc + h*HD + lane;
            g_ohhi[idx] = hb;
            g_ohlo[idx] = lb;
        }
    }
}

// =====================================================================
extern "C" void kernel_launch(void* const* d_in, const int* in_sizes, int n_in,
                              void* d_out, int out_size)
{
    const float* x      = (const float*)d_in[0];
    const float* Wqk    = (const float*)d_in[1];
    const float* Wv     = (const float*)d_in[2];
    const float* Wpos   = (const float*)d_in[3];
    const float* bpos   = (const float*)d_in[4];
    const float* Wproj  = (const float*)d_in[5];
    const float* bproj  = (const float*)d_in[6];
    const float* gating = (const float*)d_in[7];
    float* out = (float*)d_out;

    cudaFuncSetAttribute(attn_kernel, cudaFuncAttributeMaxDynamicSharedMemorySize,
                         ATTN_SMEM_BYTES);

    // 0) bf16 hi/lo conversions
    int n4x = ROWS * Cc / 4;
    cvt_x_kernel<<<(n4x + 255) / 256, 256>>>(x, n4x);
    cvt_w_kernel<<<(49152 + 16384 + 255) / 256, 256>>>(Wqk, Wv, Wproj);

    // 1) full positional softmax precompute (gate-scaled, shared by batches)
    pos_kernel<<<(Hh*Nn + 3) / 4, 128>>>(Wpos, bpos, gating);

    // 2) QKV projection on tensor cores: [19200,256] @ [768,256]^T
    dim3 g1(6, ROWS / 128);
    tc_gemm<<<g1, 256>>>(nullptr, nullptr, 0);

    // 3) fused gated attention, one CTA per (b,h)
    attn_kernel<<<BH, AW*32, ATTN_SMEM_BYTES>>>(gating);

    // 4) output projection on tensor cores + bias
    dim3 g2(2, ROWS / 128);
    tc_gemm<<<g2, 256>>>(bproj, out, 1);
}

// round 15
// speedup vs baseline: 1.1972x; 1.1732x over previous
#include <cuda_runtime.h>
#include <cuda_bf16.h>
#include <math.h>
#include <stdint.h>

// ---------------- problem constants ----------------
#define Bb 64
#define Nn 300
#define Cc 256
#define Hh 8
#define HD 32
#define BH (Bb*Hh)          // 512
#define ROWS (Bb*Nn)        // 19200
#define QR 4                // queries per warp (attention)
#define AW 8                // warps in attention CTA (2 CTAs/SM)
#define KP 33               // float pitch for K rows (conflict-free)

// ---------------- scratch (device globals; no runtime alloc) ----------------
__device__ float g_q[BH * Nn * HD];     // [b,h,n,d]
__device__ float g_k[BH * Nn * HD];
__device__ float g_v[BH * Nn * HD];
__device__ float g_posmx[Hh * Nn];      // per-(h,n) positional logit max
__device__ float g_posinv[Hh * Nn];     // g(h) / sum(exp(logit - max))
// bf16 hi/lo decompositions for tensor-core GEMMs
__device__ __align__(16) __nv_bfloat16 g_xhi[ROWS * Cc],  g_xlo[ROWS * Cc];
__device__ __align__(16) __nv_bfloat16 g_whi[768 * Cc],   g_wlo[768 * Cc];   // [Wqk;Wv]
__device__ __align__(16) __nv_bfloat16 g_pwhi[Cc * Cc],   g_pwlo[Cc * Cc];   // Wproj
__device__ __align__(16) __nv_bfloat16 g_ohhi[ROWS * Cc], g_ohlo[ROWS * Cc]; // attn out

// ---------------- packed f32x2 helpers (attention) ----------------
__device__ __forceinline__ unsigned long long pk2(float x, float y) {
    unsigned long long r;
    asm("mov.b64 %0, {%1,%2};" : "=l"(r)
        : "r"(__float_as_uint(x)), "r"(__float_as_uint(y)));
    return r;
}
__device__ __forceinline__ void fma2(unsigned long long& d,
                                     unsigned long long a, unsigned long long b) {
    asm("fma.rn.f32x2 %0, %1, %2, %0;" : "+l"(d) : "l"(a), "l"(b));
}
__device__ __forceinline__ void upk2(float& lo, float& hi, unsigned long long v) {
    uint32_t l, h;
    asm("mov.b64 {%0,%1}, %2;" : "=r"(l), "=r"(h) : "l"(v));
    lo = __uint_as_float(l); hi = __uint_as_float(h);
}

// ---------------- tensor-core + cp.async helpers (baseline PTX) -------------
__device__ __forceinline__ void mma16816(float* c, const uint32_t* a, const uint32_t* b) {
    asm volatile("mma.sync.aligned.m16n8k16.row.col.f32.bf16.bf16.f32 "
        "{%0,%1,%2,%3}, {%4,%5,%6,%7}, {%8,%9}, {%0,%1,%2,%3};"
        : "+f"(c[0]), "+f"(c[1]), "+f"(c[2]), "+f"(c[3])
        : "r"(a[0]), "r"(a[1]), "r"(a[2]), "r"(a[3]), "r"(b[0]), "r"(b[1]));
}
#define CP_ASYNC16(dst, src) \
    asm volatile("cp.async.cg.shared.global [%0], [%1], 16;" :: "r"(dst), "l"(src))
#define CP_COMMIT() asm volatile("cp.async.commit_group;" ::: "memory")
#define CP_WAIT1()  asm volatile("cp.async.wait_group 1;" ::: "memory")
#define CP_WAIT0()  asm volatile("cp.async.wait_group 0;" ::: "memory")

// =====================================================================
// fp32 -> bf16 hi/lo converters
// =====================================================================
__device__ __forceinline__ void cvt_store4(float4 v, __nv_bfloat16* hi, __nv_bfloat16* lo,
                                           size_t e) {
    __nv_bfloat16 h0 = __float2bfloat16(v.x), h1 = __float2bfloat16(v.y);
    __nv_bfloat16 h2 = __float2bfloat16(v.z), h3 = __float2bfloat16(v.w);
    __nv_bfloat16 l0 = __float2bfloat16(v.x - __bfloat162float(h0));
    __nv_bfloat16 l1 = __float2bfloat16(v.y - __bfloat162float(h1));
    __nv_bfloat16 l2 = __float2bfloat16(v.z - __bfloat162float(h2));
    __nv_bfloat16 l3 = __float2bfloat16(v.w - __bfloat162float(h3));
    __nv_bfloat162* hp = (__nv_bfloat162*)(hi + e);
    __nv_bfloat162* lp = (__nv_bfloat162*)(lo + e);
    hp[0] = __halves2bfloat162(h0, h1); hp[1] = __halves2bfloat162(h2, h3);
    lp[0] = __halves2bfloat162(l0, l1); lp[1] = __halves2bfloat162(l2, l3);
}

__global__ void cvt_x_kernel(const float* __restrict__ src, int n4) {
    int i = blockIdx.x * blockDim.x + threadIdx.x;
    if (i >= n4) return;
    cvt_store4(((const float4*)src)[i], g_xhi, g_xlo, (size_t)i * 4);
}

__global__ void cvt_w_kernel(const float* __restrict__ Wqk, const float* __restrict__ Wv,
                             const float* __restrict__ Wproj) {
    int i = blockIdx.x * blockDim.x + threadIdx.x;   // float4 index
    if (i < 49152) {
        size_t e = (size_t)i * 4;
        const float* s = (e < 512u*256u) ? (Wqk + e) : (Wv + e - 512u*256u);
        cvt_store4(*(const float4*)s, g_whi, g_wlo, e);
    } else if (i < 49152 + 16384) {
        size_t e = (size_t)(i - 49152) * 4;
        cvt_store4(((const float4*)Wproj)[i - 49152], g_pwhi, g_pwlo, e);
    }
}

// =====================================================================
// positional softmax stats (R12 version)
// =====================================================================
__global__ void pos_kernel(const float* __restrict__ Wpos,
                           const float* __restrict__ bpos,
                           const float* __restrict__ gating)
{
    int row  = blockIdx.x * 4 + (threadIdx.x >> 5);
    int lane = threadIdx.x & 31;
    if (row >= Hh * Nn) return;
    int h = row / Nn, n = row % Nn;
    float w0 = Wpos[h*3+0], w2 = Wpos[h*3+2], b = bpos[h];

    float s[10], mx = -1e30f;
    #pragma unroll
    for (int t = 0; t < 10; t++) {
        int m = t*32 + lane;
        float v = -1e30f;
        if (m < Nn) { float d = (float)(m - n); v = fmaf(w2*d, d, fmaf(w0, d, b)); }
        s[t] = v; mx = fmaxf(mx, v);
    }
    #pragma unroll
    for (int o = 16; o; o >>= 1) mx = fmaxf(mx, __shfl_xor_sync(0xffffffffu, mx, o));
    float esum = 0.f;
    #pragma unroll
    for (int t = 0; t < 10; t++) esum += __expf(s[t] - mx);
    #pragma unroll
    for (int o = 16; o; o >>= 1) esum += __shfl_xor_sync(0xffffffffu, esum, o);
    if (lane == 0) {
        float g = 1.0f / (1.0f + __expf(-gating[h]));
        g_posmx[row]  = mx;
        g_posinv[row] = g / esum;
    }
}

// =====================================================================
// mma.sync GEMM v3: cp.async 2-stage pipeline. 256 threads, 64x32/warp,
// plain LDS fragment loads (PAD=40 -> 20 words/row, conflict-free).
// D[128,128] tile of A[rows,256] @ W[ncols,256]^T, 3-term bf16 split.
// mode 0: A=g_xhi/lo, W=g_whi/lo -> scatter q/k/v. mode 1: out=D+bias.
// =====================================================================
#define PAD 40                           // bf16 elems per row (80 B)
#define TILE_CHUNK_B (128 * PAD * 2)     // 10240 B per tile per K-chunk
#define GEMM_CHUNK_B (4 * TILE_CHUNK_B)  // 40960 B per K-chunk (4 tiles)
#define GEMM_SMEM    (2 * GEMM_CHUNK_B)  // 81920 B double-buffered

__device__ __forceinline__ void gemm_stage(uint32_t sb, int buf,
                                           const __nv_bfloat16* s0,
                                           const __nv_bfloat16* s1,
                                           const __nv_bfloat16* s2,
                                           const __nv_bfloat16* s3,
                                           int k0, int tid)
{
    int r = tid >> 2, u = tid & 3;
    uint32_t base = sb + buf * GEMM_CHUNK_B + r * 80 + u * 16;
    size_t goff = (size_t)r * 256 + k0 + u * 8;
    CP_ASYNC16(base + 0*TILE_CHUNK_B,        s0 + goff);
    CP_ASYNC16(base + 0*TILE_CHUNK_B + 5120, s0 + goff + 64*256);   // 64 rows * 80B
    CP_ASYNC16(base + 1*TILE_CHUNK_B,        s1 + goff);
    CP_ASYNC16(base + 1*TILE_CHUNK_B + 5120, s1 + goff + 64*256);
    CP_ASYNC16(base + 2*TILE_CHUNK_B,        s2 + goff);
    CP_ASYNC16(base + 2*TILE_CHUNK_B + 5120, s2 + goff + 64*256);
    CP_ASYNC16(base + 3*TILE_CHUNK_B,        s3 + goff);
    CP_ASYNC16(base + 3*TILE_CHUNK_B + 5120, s3 + goff + 64*256);
    CP_COMMIT();
}

__global__ __launch_bounds__(256, 2)
void tc_gemm(const float* __restrict__ bias, float* __restrict__ out, int mode)
{
    extern __shared__ __align__(16) char gsm[];
    uint32_t sb = (uint32_t)__cvta_generic_to_shared(gsm);

    int tid = threadIdx.x, wid = tid >> 5, lane = tid & 31;
    int row0 = blockIdx.y * 128;
    int col0 = blockIdx.x * 128;
    int warpM = wid & 1;           // 2 x 64 rows
    int warpN = wid >> 1;          // 4 x 32 cols
    int g  = lane >> 2;            // fragment row group 0..7
    int tg = lane & 3;             // fragment k group

    const __nv_bfloat16 *s0, *s1, *s2, *s3;
    if (mode == 0) {
        s0 = g_xhi + (size_t)row0 * 256;  s1 = g_xlo + (size_t)row0 * 256;
        s2 = g_whi + (size_t)col0 * 256;  s3 = g_wlo + (size_t)col0 * 256;
    } else {
        s0 = g_ohhi + (size_t)row0 * 256; s1 = g_ohlo + (size_t)row0 * 256;
        s2 = g_pwhi + (size_t)col0 * 256; s3 = g_pwlo + (size_t)col0 * 256;
    }

    float acc[4][4][4];
    #pragma unroll
    for (int mt = 0; mt < 4; mt++)
        #pragma unroll
        for (int nt = 0; nt < 4; nt++)
            #pragma unroll
            for (int f = 0; f < 4; f++) acc[mt][nt][f] = 0.f;

    gemm_stage(sb, 0, s0, s1, s2, s3, 0,  tid);
    gemm_stage(sb, 1, s0, s1, s2, s3, 32, tid);

    for (int kc = 0; kc < 8; kc++) {
        if (kc < 7) CP_WAIT1(); else CP_WAIT0();
        __syncthreads();

        const char* cbase = gsm + (kc & 1) * GEMM_CHUNK_B;
        #pragma unroll
        for (int kg = 0; kg < 2; kg++) {
            int kb = kg * 16 + tg * 2;        // element offset in row
            uint32_t Ah[4][4], Al[4][4];
            #pragma unroll
            for (int mt = 0; mt < 4; mt++) {
                const char* pa = cbase + 0*TILE_CHUNK_B +
                                 (warpM*64 + mt*16 + g) * (PAD*2) + kb * 2;
                const char* pl = cbase + 1*TILE_CHUNK_B +
                                 (warpM*64 + mt*16 + g) * (PAD*2) + kb * 2;
                Ah[mt][0] = *(const uint32_t*)(pa);
                Ah[mt][1] = *(const uint32_t*)(pa + 8 * (PAD*2));
                Ah[mt][2] = *(const uint32_t*)(pa + 16);
                Ah[mt][3] = *(const uint32_t*)(pa + 8 * (PAD*2) + 16);
                Al[mt][0] = *(const uint32_t*)(pl);
                Al[mt][1] = *(const uint32_t*)(pl + 8 * (PAD*2));
                Al[mt][2] = *(const uint32_t*)(pl + 16);
                Al[mt][3] = *(const uint32_t*)(pl + 8 * (PAD*2) + 16);
            }
            uint32_t Bh[4][2], Bl[4][2];
            #pragma unroll
            for (int nt = 0; nt < 4; nt++) {
                const char* pb = cbase + 2*TILE_CHUNK_B +
                                 (warpN*32 + nt*8 + g) * (PAD*2) + kb * 2;
                const char* pbl = cbase + 3*TILE_CHUNK_B +
                                 (warpN*32 + nt*8 + g) * (PAD*2) + kb * 2;
                Bh[nt][0] = *(const uint32_t*)(pb);
                Bh[nt][1] = *(const uint32_t*)(pb + 16);
                Bl[nt][0] = *(const uint32_t*)(pbl);
                Bl[nt][1] = *(const uint32_t*)(pbl + 16);
            }
            #pragma unroll
            for (int mt = 0; mt < 4; mt++)
                #pragma unroll
                for (int nt = 0; nt < 4; nt++) {
                    mma16816(acc[mt][nt], Ah[mt], Bh[nt]);
                    mma16816(acc[mt][nt], Al[mt], Bh[nt]);
                    mma16816(acc[mt][nt], Ah[mt], Bl[nt]);
                }
        }

        if (kc < 6) {
            __syncthreads();     // everyone done reading this buffer
            gemm_stage(sb, kc & 1, s0, s1, s2, s3, (kc + 2) * 32, tid);
        }
    }

    // ---------------- epilogue ----------------
    int sec = col0 >> 8;                                  // mode0: 0=q 1=k 2=v
    int h   = ((col0 & 255) >> 5) + warpN;                // one head per warp
    #pragma unroll
    for (int mt = 0; mt < 4; mt++) {
        #pragma unroll
        for (int rr = 0; rr < 2; rr++) {
            int r = row0 + warpM*64 + mt*16 + (lane >> 2) + rr*8;
            int bidx = r / Nn, n = r % Nn;
            #pragma unroll
            for (int nt = 0; nt < 4; nt++) {
                int col = col0 + warpN*32 + nt*8 + (lane & 3)*2;
                float d0 = acc[mt][nt][rr*2 + 0];
                float d1 = acc[mt][nt][rr*2 + 1];
                if (mode == 0) {
                    float* basep = (sec == 0) ? g_q : (sec == 1) ? g_k : g_v;
                    int d = col & 31;
                    *(float2*)(basep + (((size_t)bidx*Hh + h)*Nn + n)*HD + d) =
                        make_float2(d0, d1);
                } else {
                    *(float2*)(out + (size_t)r * 256 + col) =
                        make_float2(d0 + bias[col], d1 + bias[col + 1]);
                }
            }
        }
    }
}

// =====================================================================
// Attention (R12 measured-best): one CTA per (b,h), 8 warps, QR=4,
// 2 CTAs/SM. Output stored bf16 hi/lo for the tensor-core projection.
// =====================================================================
#define SM_U64_VS2 ((Nn/2)*32)                 // 4800 u64
#define SM_F_KS    (Nn*KP)                     // 9900 f
#define ATTN_SMEM_BYTES (SM_U64_VS2*8 + (SM_F_KS + AW*32*QR + AW*QR*32)*4)

__global__ __launch_bounds__(AW*32, 2)
void attn_kernel(const float* __restrict__ Wpos,
                 const float* __restrict__ bpos,
                 const float* __restrict__ gating)
{
    extern __shared__ __align__(16) unsigned long long smu[];
    unsigned long long* vs2 = smu;                         // (V[m],V[m+1])
    float* ks  = (float*)(smu + SM_U64_VS2);               // [m*KP + d]
    float* qs  = ks + SM_F_KS;
    float* scb = qs + AW*32*QR;

    int bh = blockIdx.x;
    int h  = bh & 7, bidx = bh >> 3;
    int tid = threadIdx.x, wid = tid >> 5, lane = tid & 31;

    const float* kg = g_k + (size_t)bh * Nn * HD;
    const float* vg = g_v + (size_t)bh * Nn * HD;
    const float* qg = g_q + (size_t)bh * Nn * HD;

    for (int i = tid; i < Nn * 8; i += AW*32) {
        int m = i >> 3, d = (i & 7) * 4;
        float4 kv4 = *(const float4*)(kg + m*HD + d);
        ks[m*KP + d + 0] = kv4.x; ks[m*KP + d + 1] = kv4.y;
        ks[m*KP + d + 2] = kv4.z; ks[m*KP + d + 3] = kv4.w;
    }
    for (int i = tid; i < (Nn/2) * 8; i += AW*32) {
        int mp = i >> 3, d = (i & 7) * 4;
        float4 va = *(const float4*)(vg + (2*mp)*HD + d);
        float4 vb = *(const float4*)(vg + (2*mp+1)*HD + d);
        vs2[mp*32 + d + 0] = pk2(va.x, vb.x);
        vs2[mp*32 + d + 1] = pk2(va.y, vb.y);
        vs2[mp*32 + d + 2] = pk2(va.z, vb.z);
        vs2[mp*32 + d + 3] = pk2(va.w, vb.w);
    }
    __syncthreads();

    float g  = 1.0f / (1.0f + __expf(-gating[h]));
    float w0 = Wpos[h*3+0], w2 = Wpos[h*3+2], bps = bpos[h];
    const float scale = 0.17677669529663687f;
    float* myq  = qs  + wid * (32*QR);
    float* mysc = scb + wid * (QR*32);

    for (int n0 = wid*QR; n0 < Nn; n0 += AW*QR) {
        {
            float q0 = qg[(n0+0)*HD + lane];
            float q1 = qg[(n0+1)*HD + lane];
            float q2 = qg[(n0+2)*HD + lane];
            float q3 = qg[(n0+3)*HD + lane];
            *(float4*)&myq[lane*QR] = make_float4(q0, q1, q2, q3);
        }
        __syncwarp();

        unsigned long long acc2[2][10];
        #pragma unroll
        for (int p = 0; p < 2; p++)
            #pragma unroll
            for (int t = 0; t < 10; t++) acc2[p][t] = 0ULL;

        #pragma unroll
        for (int d = 0; d < HD; d++) {
            ulonglong2 qp = *(const ulonglong2*)&myq[d*QR];
            #pragma unroll
            for (int t = 0; t < 10; t++) {
                float kv = ks[(t*32 + lane)*KP + d];
                unsigned long long kp = pk2(kv, kv);
                fma2(acc2[0][t], qp.x, kp);
                fma2(acc2[1][t], qp.y, kp);
            }
        }

        float s[QR][10], inv[QR], pmx[QR], pw[QR];
        #pragma unroll
        for (int qq = 0; qq < QR; qq++) {
            int n = n0 + qq;
            float mx = -1e30f;
            #pragma unroll
            for (int t = 0; t < 10; t++) {
                float lo, hi; upk2(lo, hi, acc2[qq >> 1][t]);
                float v = (qq & 1) ? hi : lo;
                int m = t*32 + lane;
                v = (m < Nn) ? v * scale : -1e30f;
                s[qq][t] = v; mx = fmaxf(mx, v);
            }
            #pragma unroll
            for (int o = 16; o; o >>= 1) mx = fmaxf(mx, __shfl_xor_sync(0xffffffffu, mx, o));
            float esum = 0.f;
            #pragma unroll
            for (int t = 0; t < 10; t++) { s[qq][t] = __expf(s[qq][t] - mx); esum += s[qq][t]; }
            #pragma unroll
            for (int o = 16; o; o >>= 1) esum += __shfl_xor_sync(0xffffffffu, esum, o);
            inv[qq] = (1.0f - g) / esum;
            pmx[qq] = g_posmx[h*Nn + n];
            pw[qq]  = g_posinv[h*Nn + n];
        }

        unsigned long long o2[QR];
        #pragma unroll
        for (int qq = 0; qq < QR; qq++) o2[qq] = 0ULL;

        #pragma unroll
        for (int t = 0; t < 10; t++) {
            int m = t*32 + lane;
            float fm = (float)m;
            #pragma unroll
            for (int qq = 0; qq < QR; qq++) {
                float av = 0.f;
                if (m < Nn) {
                    float dd = fm - (float)(n0 + qq);
                    float pe = __expf(fmaf(w2*dd, dd, fmaf(w0, dd, bps)) - pmx[qq]) * pw[qq];
                    av = fmaf(s[qq][t], inv[qq], pe);
                }
                mysc[qq*32 + lane] = av;
            }
            __syncwarp();
            int j4max = (t < 9) ? 8 : 3;
            for (int j4 = 0; j4 < j4max; j4++) {
                unsigned long long vp0 = vs2[(t*16 + 2*j4 + 0)*32 + lane];
                unsigned long long vp1 = vs2[(t*16 + 2*j4 + 1)*32 + lane];
                #pragma unroll
                for (int qq = 0; qq < QR; qq++) {
                    ulonglong2 a4 = *(const ulonglong2*)&mysc[qq*32 + j4*4];
                    fma2(o2[qq], a4.x, vp0);
                    fma2(o2[qq], a4.y, vp1);
                }
            }
            __syncwarp();
        }

        #pragma unroll
        for (int qq = 0; qq < QR; qq++) {
            float lo, hi; upk2(lo, hi, o2[qq]);
            float val = lo + hi;
            __nv_bfloat16 hb = __float2bfloat16(val);
            __nv_bfloat16 lb = __float2bfloat16(val - __bfloat162float(hb));
            size_t idx = ((size_t)bidx*Nn + (n0+qq))*Cc + h*HD + lane;
            g_ohhi[idx] = hb;
            g_ohlo[idx] = lb;
        }
    }
}

// =====================================================================
extern "C" void kernel_launch(void* const* d_in, const int* in_sizes, int n_in,
                              void* d_out, int out_size)
{
    const float* x      = (const float*)d_in[0];
    const float* Wqk    = (const float*)d_in[1];
    const float* Wv     = (const float*)d_in[2];
    const float* Wpos   = (const float*)d_in[3];
    const float* bpos   = (const float*)d_in[4];
    const float* Wproj  = (const float*)d_in[5];
    const float* bproj  = (const float*)d_in[6];
    const float* gating = (const float*)d_in[7];
    float* out = (float*)d_out;

    cudaFuncSetAttribute(attn_kernel, cudaFuncAttributeMaxDynamicSharedMemorySize,
                         ATTN_SMEM_BYTES);
    cudaFuncSetAttribute(tc_gemm, cudaFuncAttributeMaxDynamicSharedMemorySize,
                         GEMM_SMEM);

    // 0) bf16 hi/lo conversions
    int n4x = ROWS * Cc / 4;
    cvt_x_kernel<<<(n4x + 255) / 256, 256>>>(x, n4x);
    cvt_w_kernel<<<(49152 + 16384 + 255) / 256, 256>>>(Wqk, Wv, Wproj);

    // 1) positional softmax stats
    pos_kernel<<<(Hh*Nn + 3) / 4, 128>>>(Wpos, bpos, gating);

    // 2) QKV projection on tensor cores: [19200,256] @ [768,256]^T
    dim3 g1(6, ROWS / 128);
    tc_gemm<<<g1, 256, GEMM_SMEM>>>(nullptr, nullptr, 0);

    // 3) fused gated attention, one CTA per (b,h)
    attn_kernel<<<BH, AW*32, ATTN_SMEM_BYTES>>>(Wpos, bpos, gating);

    // 4) output projection on tensor cores + bias
    dim3 g2(2, ROWS / 128);
    tc_gemm<<<g2, 256, GEMM_SMEM>>>(bproj, out, 1);
}

// round 16
// speedup vs baseline: 1.6672x; 1.3926x over previous
#include <cuda_runtime.h>
#include <cuda_bf16.h>
#include <math.h>
#include <stdint.h>

// ---------------- problem constants ----------------
#define Bb 64
#define Nn 300
#define Cc 256
#define Hh 8
#define HD 32
#define BH (Bb*Hh)          // 512
#define ROWS (Bb*Nn)        // 19200

// ---------------- scratch (device globals; no runtime alloc) ----------------
__device__ float g_q[BH * Nn * HD];     // [b,h,n,d]
__device__ float g_k[BH * Nn * HD];
__device__ float g_v[BH * Nn * HD];
// gate-scaled positional weights, bf16 hi/lo, [h][304][320]
__device__ __align__(16) __nv_bfloat16 g_posbhi[Hh * 304 * 320];
__device__ __align__(16) __nv_bfloat16 g_posblo[Hh * 304 * 320];
// bf16 hi/lo decompositions for tensor-core GEMMs
__device__ __align__(16) __nv_bfloat16 g_xhi[ROWS * Cc],  g_xlo[ROWS * Cc];
__device__ __align__(16) __nv_bfloat16 g_whi[768 * Cc],   g_wlo[768 * Cc];   // [Wqk;Wv]
__device__ __align__(16) __nv_bfloat16 g_pwhi[Cc * Cc],   g_pwlo[Cc * Cc];   // Wproj
__device__ __align__(16) __nv_bfloat16 g_ohhi[ROWS * Cc], g_ohlo[ROWS * Cc]; // attn out

// ---------------- tensor-core + cp.async helpers (baseline PTX) -------------
__device__ __forceinline__ void mma16816(float* c, const uint32_t* a, const uint32_t* b) {
    asm volatile("mma.sync.aligned.m16n8k16.row.col.f32.bf16.bf16.f32 "
        "{%0,%1,%2,%3}, {%4,%5,%6,%7}, {%8,%9}, {%0,%1,%2,%3};"
        : "+f"(c[0]), "+f"(c[1]), "+f"(c[2]), "+f"(c[3])
        : "r"(a[0]), "r"(a[1]), "r"(a[2]), "r"(a[3]), "r"(b[0]), "r"(b[1]));
}
#define CP_ASYNC16(dst, src) \
    asm volatile("cp.async.cg.shared.global [%0], [%1], 16;" :: "r"(dst), "l"(src))
#define CP_COMMIT() asm volatile("cp.async.commit_group;" ::: "memory")
#define CP_WAIT1()  asm volatile("cp.async.wait_group 1;" ::: "memory")
#define CP_WAIT0()  asm volatile("cp.async.wait_group 0;" ::: "memory")

// pack two fp32 -> bf16x2 (lo = x, hi = y), plus hi/lo split helpers
__device__ __forceinline__ uint32_t bfpack(float x, float y) {
    uint32_t r;
    asm("cvt.rn.bf16x2.f32 %0, %1, %2;" : "=r"(r) : "f"(y), "f"(x));
    return r;
}
__device__ __forceinline__ void bfsplit(uint32_t& hi, uint32_t& lo, float x, float y) {
    hi = bfpack(x, y);
    float hx = __uint_as_float(hi << 16);
    float hy = __uint_as_float(hi & 0xffff0000u);
    lo = bfpack(x - hx, y - hy);
}

// =====================================================================
// fp32 -> bf16 hi/lo converters (x and weights)
// =====================================================================
__device__ __forceinline__ void cvt_store4(float4 v, __nv_bfloat16* hi, __nv_bfloat16* lo,
                                           size_t e) {
    uint32_t h0, l0, h1, l1;
    bfsplit(h0, l0, v.x, v.y);
    bfsplit(h1, l1, v.z, v.w);
    *(uint2*)(hi + e) = make_uint2(h0, h1);
    *(uint2*)(lo + e) = make_uint2(l0, l1);
}

__global__ void cvt_x_kernel(const float* __restrict__ src, int n4) {
    int i = blockIdx.x * blockDim.x + threadIdx.x;
    if (i >= n4) return;
    cvt_store4(((const float4*)src)[i], g_xhi, g_xlo, (size_t)i * 4);
}

__global__ void cvt_w_kernel(const float* __restrict__ Wqk, const float* __restrict__ Wv,
                             const float* __restrict__ Wproj) {
    int i = blockIdx.x * blockDim.x + threadIdx.x;   // float4 index
    if (i < 49152) {
        size_t e = (size_t)i * 4;
        const float* s = (e < 512u*256u) ? (Wqk + e) : (Wv + e - 512u*256u);
        cvt_store4(*(const float4*)s, g_whi, g_wlo, e);
    } else if (i < 49152 + 16384) {
        size_t e = (size_t)(i - 49152) * 4;
        cvt_store4(((const float4*)Wproj)[i - 49152], g_pwhi, g_pwlo, e);
    }
}

// =====================================================================
// positional softmax -> full gate-scaled bf16 hi/lo tensor [h][304][320]
// =====================================================================
__global__ void pos_kernel(const float* __restrict__ Wpos,
                           const float* __restrict__ bpos,
                           const float* __restrict__ gating)
{
    int row  = blockIdx.x * 4 + (threadIdx.x >> 5);   // h*304 + n
    int lane = threadIdx.x & 31;
    if (row >= Hh * 304) return;
    int h = row / 304, n = row % 304;
    __nv_bfloat16* dh = g_posbhi + (size_t)row * 320;
    __nv_bfloat16* dl = g_posblo + (size_t)row * 320;

    if (n >= Nn) {
        for (int t = 0; t < 10; t++) {
            dh[t*32 + lane] = __float2bfloat16(0.f);
            dl[t*32 + lane] = __float2bfloat16(0.f);
        }
        return;
    }
    float w0 = Wpos[h*3+0], w2 = Wpos[h*3+2], b = bpos[h];
    float s[10], mx = -1e30f;
    #pragma unroll
    for (int t = 0; t < 10; t++) {
        int m = t*32 + lane;
        float v = -1e30f;
        if (m < Nn) { float d = (float)(m - n); v = fmaf(w2*d, d, fmaf(w0, d, b)); }
        s[t] = v; mx = fmaxf(mx, v);
    }
    #pragma unroll
    for (int o = 16; o; o >>= 1) mx = fmaxf(mx, __shfl_xor_sync(0xffffffffu, mx, o));
    float esum = 0.f;
    #pragma unroll
    for (int t = 0; t < 10; t++) { s[t] = __expf(s[t] - mx); esum += s[t]; }
    #pragma unroll
    for (int o = 16; o; o >>= 1) esum += __shfl_xor_sync(0xffffffffu, esum, o);
    float g = 1.0f / (1.0f + __expf(-gating[h]));
    float inv = g / esum;
    #pragma unroll
    for (int t = 0; t < 10; t++) {
        int m = t*32 + lane;
        float v = (m < Nn) ? s[t] * inv : 0.f;
        __nv_bfloat16 hb = __float2bfloat16(v);
        __nv_bfloat16 lb = __float2bfloat16(v - __bfloat162float(hb));
        dh[m] = hb; dl[m] = lb;
    }
}

// =====================================================================
// mma.sync GEMM (R15 measured-best): cp.async 2-stage, 256 thr, 64x32/warp
// =====================================================================
#define PAD 40
#define TILE_CHUNK_B (128 * PAD * 2)
#define GEMM_CHUNK_B (4 * TILE_CHUNK_B)
#define GEMM_SMEM    (2 * GEMM_CHUNK_B)

__device__ __forceinline__ void gemm_stage(uint32_t sb, int buf,
                                           const __nv_bfloat16* s0,
                                           const __nv_bfloat16* s1,
                                           const __nv_bfloat16* s2,
                                           const __nv_bfloat16* s3,
                                           int k0, int tid)
{
    int r = tid >> 2, u = tid & 3;
    uint32_t base = sb + buf * GEMM_CHUNK_B + r * 80 + u * 16;
    size_t goff = (size_t)r * 256 + k0 + u * 8;
    CP_ASYNC16(base + 0*TILE_CHUNK_B,        s0 + goff);
    CP_ASYNC16(base + 0*TILE_CHUNK_B + 5120, s0 + goff + 64*256);
    CP_ASYNC16(base + 1*TILE_CHUNK_B,        s1 + goff);
    CP_ASYNC16(base + 1*TILE_CHUNK_B + 5120, s1 + goff + 64*256);
    CP_ASYNC16(base + 2*TILE_CHUNK_B,        s2 + goff);
    CP_ASYNC16(base + 2*TILE_CHUNK_B + 5120, s2 + goff + 64*256);
    CP_ASYNC16(base + 3*TILE_CHUNK_B,        s3 + goff);
    CP_ASYNC16(base + 3*TILE_CHUNK_B + 5120, s3 + goff + 64*256);
    CP_COMMIT();
}

__global__ __launch_bounds__(256, 2)
void tc_gemm(const float* __restrict__ bias, float* __restrict__ out, int mode)
{
    extern __shared__ __align__(16) char gsm[];
    uint32_t sb = (uint32_t)__cvta_generic_to_shared(gsm);

    int tid = threadIdx.x, wid = tid >> 5, lane = tid & 31;
    int row0 = blockIdx.y * 128;
    int col0 = blockIdx.x * 128;
    int warpM = wid & 1;
    int warpN = wid >> 1;
    int g  = lane >> 2;
    int tg = lane & 3;

    const __nv_bfloat16 *s0, *s1, *s2, *s3;
    if (mode == 0) {
        s0 = g_xhi + (size_t)row0 * 256;  s1 = g_xlo + (size_t)row0 * 256;
        s2 = g_whi + (size_t)col0 * 256;  s3 = g_wlo + (size_t)col0 * 256;
    } else {
        s0 = g_ohhi + (size_t)row0 * 256; s1 = g_ohlo + (size_t)row0 * 256;
        s2 = g_pwhi + (size_t)col0 * 256; s3 = g_pwlo + (size_t)col0 * 256;
    }

    float acc[4][4][4];
    #pragma unroll
    for (int mt = 0; mt < 4; mt++)
        #pragma unroll
        for (int nt = 0; nt < 4; nt++)
            #pragma unroll
            for (int f = 0; f < 4; f++) acc[mt][nt][f] = 0.f;

    gemm_stage(sb, 0, s0, s1, s2, s3, 0,  tid);
    gemm_stage(sb, 1, s0, s1, s2, s3, 32, tid);

    for (int kc = 0; kc < 8; kc++) {
        if (kc < 7) CP_WAIT1(); else CP_WAIT0();
        __syncthreads();

        const char* cbase = gsm + (kc & 1) * GEMM_CHUNK_B;
        #pragma unroll
        for (int kg = 0; kg < 2; kg++) {
            int kb = kg * 16 + tg * 2;
            uint32_t Ah[4][4], Al[4][4];
            #pragma unroll
            for (int mt = 0; mt < 4; mt++) {
                const char* pa = cbase + 0*TILE_CHUNK_B +
                                 (warpM*64 + mt*16 + g) * (PAD*2) + kb * 2;
                const char* pl = cbase + 1*TILE_CHUNK_B +
                                 (warpM*64 + mt*16 + g) * (PAD*2) + kb * 2;
                Ah[mt][0] = *(const uint32_t*)(pa);
                Ah[mt][1] = *(const uint32_t*)(pa + 8 * (PAD*2));
                Ah[mt][2] = *(const uint32_t*)(pa + 16);
                Ah[mt][3] = *(const uint32_t*)(pa + 8 * (PAD*2) + 16);
                Al[mt][0] = *(const uint32_t*)(pl);
                Al[mt][1] = *(const uint32_t*)(pl + 8 * (PAD*2));
                Al[mt][2] = *(const uint32_t*)(pl + 16);
                Al[mt][3] = *(const uint32_t*)(pl + 8 * (PAD*2) + 16);
            }
            uint32_t Bh[4][2], Bl[4][2];
            #pragma unroll
            for (int nt = 0; nt < 4; nt++) {
                const char* pb = cbase + 2*TILE_CHUNK_B +
                                 (warpN*32 + nt*8 + g) * (PAD*2) + kb * 2;
                const char* pbl = cbase + 3*TILE_CHUNK_B +
                                 (warpN*32 + nt*8 + g) * (PAD*2) + kb * 2;
                Bh[nt][0] = *(const uint32_t*)(pb);
                Bh[nt][1] = *(const uint32_t*)(pb + 16);
                Bl[nt][0] = *(const uint32_t*)(pbl);
                Bl[nt][1] = *(const uint32_t*)(pbl + 16);
            }
            #pragma unroll
            for (int mt = 0; mt < 4; mt++)
                #pragma unroll
                for (int nt = 0; nt < 4; nt++) {
                    mma16816(acc[mt][nt], Ah[mt], Bh[nt]);
                    mma16816(acc[mt][nt], Al[mt], Bh[nt]);
                    mma16816(acc[mt][nt], Ah[mt], Bl[nt]);
                }
        }

        if (kc < 6) {
            __syncthreads();
            gemm_stage(sb, kc & 1, s0, s1, s2, s3, (kc + 2) * 32, tid);
        }
    }

    int sec = col0 >> 8;
    int h   = ((col0 & 255) >> 5) + warpN;
    #pragma unroll
    for (int mt = 0; mt < 4; mt++) {
        #pragma unroll
        for (int rr = 0; rr < 2; rr++) {
            int r = row0 + warpM*64 + mt*16 + (lane >> 2) + rr*8;
            int bidx = r / Nn, n = r % Nn;
            #pragma unroll
            for (int nt = 0; nt < 4; nt++) {
                int col = col0 + warpN*32 + nt*8 + (lane & 3)*2;
                float d0 = acc[mt][nt][rr*2 + 0];
                float d1 = acc[mt][nt][rr*2 + 1];
                if (mode == 0) {
                    float* basep = (sec == 0) ? g_q : (sec == 1) ? g_k : g_v;
                    int d = col & 31;
                    *(float2*)(basep + (((size_t)bidx*Hh + h)*Nn + n)*HD + d) =
                        make_float2(d0, d1);
                } else {
                    *(float2*)(out + (size_t)r * 256 + col) =
                        make_float2(d0 + bias[col], d1 + bias[col + 1]);
                }
            }
        }
    }
}

// =====================================================================
// Flash-style mma attention: 1 CTA per (b,h), 8 warps, 2 CTAs/SM.
// 3 passes x 16-query tiles/warp; keys in 5 blocks of 64 (padded 320).
// QK and AV via 3-term bf16 mma; online softmax in C-fragments;
// gated pos term accumulated separately from precomputed bf16 tensor.
// =====================================================================
#define PADK 40
#define PADV 72
#define NKB 5

__global__ __launch_bounds__(256, 2)
void attn_mma(const float* __restrict__ gating)
{
    __shared__ __align__(16) __nv_bfloat16 kbhi[64*PADK], kblo[64*PADK];
    __shared__ __align__(16) __nv_bfloat16 vthi[32*PADV], vtlo[32*PADV];

    int bh = blockIdx.x, h = bh & 7, bidx = bh >> 3;
    int tid = threadIdx.x, wid = tid >> 5, lane = tid & 31;
    int g = lane >> 2, tg = lane & 3;

    const float* qg = g_q + (size_t)bh * Nn * HD;
    const float* kg = g_k + (size_t)bh * Nn * HD;
    const float* vg = g_v + (size_t)bh * Nn * HD;
    float gt = 1.0f / (1.0f + __expf(-gating[h]));
    float onemg = 1.0f - gt;
    const __nv_bfloat16* pbh = g_posbhi + (size_t)h * 304 * 320;
    const __nv_bfloat16* pbl = g_posblo + (size_t)h * 304 * 320;
    const float scale = 0.17677669529663687f;   // 1/sqrt(32)

    // staging thread mapping
    int sr = tid >> 2, sc8 = (tid & 3) * 8;

    for (int pass = 0; pass < 3; pass++) {
        int n0 = pass*128 + wid*16;
        bool active = (n0 < Nn);
        int rg  = n0 + g;     if (rg  > Nn-1) rg  = Nn-1;
        int rg8 = n0 + g + 8; if (rg8 > Nn-1) rg8 = Nn-1;

        // Q A-frags (hi/lo), scale folded
        uint32_t qhi[2][4], qlo[2][4];
        if (active) {
            #pragma unroll
            for (int ks = 0; ks < 2; ks++) {
                float2 f;
                f = *(const float2*)(qg + rg *32 + ks*16 + 2*tg);
                bfsplit(qhi[ks][0], qlo[ks][0], f.x*scale, f.y*scale);
                f = *(const float2*)(qg + rg8*32 + ks*16 + 2*tg);
                bfsplit(qhi[ks][1], qlo[ks][1], f.x*scale, f.y*scale);
                f = *(const float2*)(qg + rg *32 + ks*16 + 2*tg + 8);
                bfsplit(qhi[ks][2], qlo[ks][2], f.x*scale, f.y*scale);
                f = *(const float2*)(qg + rg8*32 + ks*16 + 2*tg + 8);
                bfsplit(qhi[ks][3], qlo[ks][3], f.x*scale, f.y*scale);
            }
        }

        float O1[4][4], O2[4][4];
        #pragma unroll
        for (int dt = 0; dt < 4; dt++)
            #pragma unroll
            for (int f = 0; f < 4; f++) { O1[dt][f] = 0.f; O2[dt][f] = 0.f; }
        float mrun0 = -1e30f, mrun1 = -1e30f, lrun0 = 0.f, lrun1 = 0.f;

        for (int blk = 0; blk < NKB; blk++) {
            __syncthreads();     // previous compute done before restaging
            // ---- stage K block (hi/lo) and V block transposed (hi/lo) ----
            {
                int m = blk*64 + sr;
                float4 f0, f1;
                if (m < Nn) {
                    f0 = *(const float4*)(kg + (size_t)m*32 + sc8);
                    f1 = *(const float4*)(kg + (size_t)m*32 + sc8 + 4);
                } else { f0 = make_float4(0,0,0,0); f1 = f0; }
                uint32_t h0,l0,h1,l1,h2,l2,h3,l3;
                bfsplit(h0,l0,f0.x,f0.y); bfsplit(h1,l1,f0.z,f0.w);
                bfsplit(h2,l2,f1.x,f1.y); bfsplit(h3,l3,f1.z,f1.w);
                *(uint4*)(kbhi + sr*PADK + sc8) = make_uint4(h0,h1,h2,h3);
                *(uint4*)(kblo + sr*PADK + sc8) = make_uint4(l0,l1,l2,l3);

                if (m < Nn) {
                    f0 = *(const float4*)(vg + (size_t)m*32 + sc8);
                    f1 = *(const float4*)(vg + (size_t)m*32 + sc8 + 4);
                } else { f0 = make_float4(0,0,0,0); f1 = f0; }
                float vv[8] = {f0.x,f0.y,f0.z,f0.w,f1.x,f1.y,f1.z,f1.w};
                #pragma unroll
                for (int j = 0; j < 8; j++) {
                    __nv_bfloat16 hb = __float2bfloat16(vv[j]);
                    __nv_bfloat16 lb = __float2bfloat16(vv[j] - __bfloat162float(hb));
                    vthi[(sc8+j)*PADV + sr] = hb;
                    vtlo[(sc8+j)*PADV + sr] = lb;
                }
            }
            __syncthreads();

            if (active) {
                // ---- QK: S[nt][4] over 8 n8-tiles ----
                float S[8][4];
                #pragma unroll
                for (int nt = 0; nt < 8; nt++)
                    #pragma unroll
                    for (int f = 0; f < 4; f++) S[nt][f] = 0.f;
                #pragma unroll
                for (int nt = 0; nt < 8; nt++) {
                    #pragma unroll
                    for (int ks = 0; ks < 2; ks++) {
                        const char* pb  = (const char*)kbhi +
                            ((nt*8 + g)*PADK + ks*16 + tg*2) * 2;
                        const char* pbl2 = (const char*)kblo +
                            ((nt*8 + g)*PADK + ks*16 + tg*2) * 2;
                        uint32_t Bh[2] = { *(const uint32_t*)pb,
                                           *(const uint32_t*)(pb + 16) };
                        uint32_t Bl[2] = { *(const uint32_t*)pbl2,
                                           *(const uint32_t*)(pbl2 + 16) };
                        mma16816(S[nt], qhi[ks], Bh);
                        mma16816(S[nt], qlo[ks], Bh);
                        mma16816(S[nt], qhi[ks], Bl);
                    }
                }
                // mask padded keys (only last block)
                if (blk == NKB-1) {
                    #pragma unroll
                    for (int nt = 0; nt < 8; nt++) {
                        int key = blk*64 + nt*8 + 2*tg;
                        if (key   >= Nn) { S[nt][0] = -1e30f; S[nt][2] = -1e30f; }
                        if (key+1 >= Nn) { S[nt][1] = -1e30f; S[nt][3] = -1e30f; }
                    }
                }
                // ---- online softmax ----
                float bm0 = -1e30f, bm1 = -1e30f;
                #pragma unroll
                for (int nt = 0; nt < 8; nt++) {
                    bm0 = fmaxf(bm0, fmaxf(S[nt][0], S[nt][1]));
                    bm1 = fmaxf(bm1, fmaxf(S[nt][2], S[nt][3]));
                }
                bm0 = fmaxf(bm0, __shfl_xor_sync(0xffffffffu, bm0, 1));
                bm0 = fmaxf(bm0, __shfl_xor_sync(0xffffffffu, bm0, 2));
                bm1 = fmaxf(bm1, __shfl_xor_sync(0xffffffffu, bm1, 1));
                bm1 = fmaxf(bm1, __shfl_xor_sync(0xffffffffu, bm1, 2));
                float mn0 = fmaxf(mrun0, bm0), mn1 = fmaxf(mrun1, bm1);
                float fc0 = __expf(mrun0 - mn0), fc1 = __expf(mrun1 - mn1);
                mrun0 = mn0; mrun1 = mn1;
                float ls0 = 0.f, ls1 = 0.f;
                #pragma unroll
                for (int nt = 0; nt < 8; nt++) {
                    S[nt][0] = __expf(S[nt][0] - mn0); ls0 += S[nt][0];
                    S[nt][1] = __expf(S[nt][1] - mn0); ls0 += S[nt][1];
                    S[nt][2] = __expf(S[nt][2] - mn1); ls1 += S[nt][2];
                    S[nt][3] = __expf(S[nt][3] - mn1); ls1 += S[nt][3];
                }
                ls0 += __shfl_xor_sync(0xffffffffu, ls0, 1);
                ls0 += __shfl_xor_sync(0xffffffffu, ls0, 2);
                ls1 += __shfl_xor_sync(0xffffffffu, ls1, 1);
                ls1 += __shfl_xor_sync(0xffffffffu, ls1, 2);
                lrun0 = lrun0*fc0 + ls0;
                lrun1 = lrun1*fc1 + ls1;
                #pragma unroll
                for (int dt = 0; dt < 4; dt++) {
                    O1[dt][0] *= fc0; O1[dt][1] *= fc0;
                    O1[dt][2] *= fc1; O1[dt][3] *= fc1;
                }
                // ---- AV (soft + pos) over 4 k16 steps ----
                #pragma unroll
                for (int j = 0; j < 4; j++) {
                    uint32_t phi[4], plo[4];
                    bfsplit(phi[0], plo[0], S[2*j][0],   S[2*j][1]);
                    bfsplit(phi[1], plo[1], S[2*j][2],   S[2*j][3]);
                    bfsplit(phi[2], plo[2], S[2*j+1][0], S[2*j+1][1]);
                    bfsplit(phi[3], plo[3], S[2*j+1][2], S[2*j+1][3]);
                    int keyb = blk*64 + j*16 + 2*tg;
                    uint32_t pph[4], ppl[4];
                    pph[0] = *(const uint32_t*)(pbh + (size_t)(n0+g  )*320 + keyb);
                    pph[1] = *(const uint32_t*)(pbh + (size_t)(n0+g+8)*320 + keyb);
                    pph[2] = *(const uint32_t*)(pbh + (size_t)(n0+g  )*320 + keyb + 8);
                    pph[3] = *(const uint32_t*)(pbh + (size_t)(n0+g+8)*320 + keyb + 8);
                    ppl[0] = *(const uint32_t*)(pbl + (size_t)(n0+g  )*320 + keyb);
                    ppl[1] = *(const uint32_t*)(pbl + (size_t)(n0+g+8)*320 + keyb);
                    ppl[2] = *(const uint32_t*)(pbl + (size_t)(n0+g  )*320 + keyb + 8);
                    ppl[3] = *(const uint32_t*)(pbl + (size_t)(n0+g+8)*320 + keyb + 8);
                    #pragma unroll
                    for (int dt = 0; dt < 4; dt++) {
                        const char* pv = (const char*)vthi +
                            ((dt*8 + g)*PADV + j*16 + tg*2) * 2;
                        const char* pvl = (const char*)vtlo +
                            ((dt*8 + g)*PADV + j*16 + tg*2) * 2;
                        uint32_t Vh[2] = { *(const uint32_t*)pv,
                                           *(const uint32_t*)(pv + 16) };
                        uint32_t Vl[2] = { *(const uint32_t*)pvl,
                                           *(const uint32_t*)(pvl + 16) };
                        mma16816(O1[dt], phi, Vh);
                        mma16816(O1[dt], plo, Vh);
                        mma16816(O1[dt], phi, Vl);
                        mma16816(O2[dt], pph, Vh);
                        mma16816(O2[dt], ppl, Vh);
                        mma16816(O2[dt], pph, Vl);
                    }
                }
            }
        }

        // ---- epilogue: out = (1-g)/l * O1 + O2, write bf16 hi/lo ----
        if (active) {
            float r0 = onemg / lrun0, r1 = onemg / lrun1;
            #pragma unroll
            for (int dt = 0; dt < 4; dt++) {
                int d = dt*8 + tg*2;
                if (n0 + g < Nn) {
                    float v0 = fmaf(O1[dt][0], r0, O2[dt][0]);
                    float v1 = fmaf(O1[dt][1], r0, O2[dt][1]);
                    uint32_t hb, lb; bfsplit(hb, lb, v0, v1);
                    size_t e = ((size_t)bidx*Nn + n0+g)*Cc + h*HD + d;
                    *(uint32_t*)(g_ohhi + e) = hb;
                    *(uint32_t*)(g_ohlo + e) = lb;
                }
                if (n0 + g + 8 < Nn) {
                    float v0 = fmaf(O1[dt][2], r1, O2[dt][2]);
                    float v1 = fmaf(O1[dt][3], r1, O2[dt][3]);
                    uint32_t hb, lb; bfsplit(hb, lb, v0, v1);
                    size_t e = ((size_t)bidx*Nn + n0+g+8)*Cc + h*HD + d;
                    *(uint32_t*)(g_ohhi + e) = hb;
                    *(uint32_t*)(g_ohlo + e) = lb;
                }
            }
        }
    }
}

// =====================================================================
extern "C" void kernel_launch(void* const* d_in, const int* in_sizes, int n_in,
                              void* d_out, int out_size)
{
    const float* x      = (const float*)d_in[0];
    const float* Wqk    = (const float*)d_in[1];
    const float* Wv     = (const float*)d_in[2];
    const float* Wpos   = (const float*)d_in[3];
    const float* bpos   = (const float*)d_in[4];
    const float* Wproj  = (const float*)d_in[5];
    const float* bproj  = (const float*)d_in[6];
    const float* gating = (const float*)d_in[7];
    float* out = (float*)d_out;

    cudaFuncSetAttribute(tc_gemm, cudaFuncAttributeMaxDynamicSharedMemorySize,
                         GEMM_SMEM);

    // 0) bf16 hi/lo conversions
    int n4x = ROWS * Cc / 4;
    cvt_x_kernel<<<(n4x + 255) / 256, 256>>>(x, n4x);
    cvt_w_kernel<<<(49152 + 16384 + 255) / 256, 256>>>(Wqk, Wv, Wproj);

    // 1) gate-scaled positional softmax tensor (bf16 hi/lo)
    pos_kernel<<<(Hh*304 + 3) / 4, 128>>>(Wpos, bpos, gating);

    // 2) QKV projection on tensor cores
    dim3 g1(6, ROWS / 128);
    tc_gemm<<<g1, 256, GEMM_SMEM>>>(nullptr, nullptr, 0);

    // 3) flash-style mma attention, one CTA per (b,h)
    attn_mma<<<BH, 256>>>(gating);

    // 4) output projection on tensor cores + bias
    dim3 g2(2, ROWS / 128);
    tc_gemm<<<g2, 256, GEMM_SMEM>>>(bproj, out, 1);
}

// round 17
// speedup vs baseline: 1.9111x; 1.1463x over previous
#include <cuda_runtime.h>
#include <cuda_bf16.h>
#include <math.h>
#include <stdint.h>

// ---------------- problem constants ----------------
#define Bb 64
#define Nn 300
#define Cc 256
#define Hh 8
#define HD 32
#define BH (Bb*Hh)          // 512
#define ROWS (Bb*Nn)        // 19200

// ---------------- scratch (device globals; no runtime alloc) ----------------
__device__ float g_q[BH * Nn * HD];     // [b,h,n,d]
__device__ float g_k[BH * Nn * HD];
__device__ float g_v[BH * Nn * HD];
// gate-scaled positional weights, bf16 hi/lo, [h][304][320]
__device__ __align__(16) __nv_bfloat16 g_posbhi[Hh * 304 * 320];
__device__ __align__(16) __nv_bfloat16 g_posblo[Hh * 304 * 320];
// bf16 hi/lo decompositions for tensor-core GEMMs
__device__ __align__(16) __nv_bfloat16 g_xhi[ROWS * Cc],  g_xlo[ROWS * Cc];
__device__ __align__(16) __nv_bfloat16 g_whi[768 * Cc],   g_wlo[768 * Cc];   // [Wqk;Wv]
__device__ __align__(16) __nv_bfloat16 g_pwhi[Cc * Cc],   g_pwlo[Cc * Cc];   // Wproj
__device__ __align__(16) __nv_bfloat16 g_ohhi[ROWS * Cc], g_ohlo[ROWS * Cc]; // attn out

// ---------------- tensor-core + cp.async helpers (baseline PTX) -------------
__device__ __forceinline__ void mma16816(float* c, const uint32_t* a, const uint32_t* b) {
    asm volatile("mma.sync.aligned.m16n8k16.row.col.f32.bf16.bf16.f32 "
        "{%0,%1,%2,%3}, {%4,%5,%6,%7}, {%8,%9}, {%0,%1,%2,%3};"
        : "+f"(c[0]), "+f"(c[1]), "+f"(c[2]), "+f"(c[3])
        : "r"(a[0]), "r"(a[1]), "r"(a[2]), "r"(a[3]), "r"(b[0]), "r"(b[1]));
}
#define CP_ASYNC16(dst, src) \
    asm volatile("cp.async.cg.shared.global [%0], [%1], 16;" :: "r"(dst), "l"(src))
#define CP_COMMIT() asm volatile("cp.async.commit_group;" ::: "memory")
#define CP_WAIT1()  asm volatile("cp.async.wait_group 1;" ::: "memory")
#define CP_WAIT0()  asm volatile("cp.async.wait_group 0;" ::: "memory")

// pack two fp32 -> bf16x2 (lo = x, hi = y), plus hi/lo split helpers
__device__ __forceinline__ uint32_t bfpack(float x, float y) {
    uint32_t r;
    asm("cvt.rn.bf16x2.f32 %0, %1, %2;" : "=r"(r) : "f"(y), "f"(x));
    return r;
}
__device__ __forceinline__ void bfsplit(uint32_t& hi, uint32_t& lo, float x, float y) {
    hi = bfpack(x, y);
    float hx = __uint_as_float(hi << 16);
    float hy = __uint_as_float(hi & 0xffff0000u);
    lo = bfpack(x - hx, y - hy);
}

// =====================================================================
// fp32 -> bf16 hi/lo converters (x and weights)
// =====================================================================
__device__ __forceinline__ void cvt_store4(float4 v, __nv_bfloat16* hi, __nv_bfloat16* lo,
                                           size_t e) {
    uint32_t h0, l0, h1, l1;
    bfsplit(h0, l0, v.x, v.y);
    bfsplit(h1, l1, v.z, v.w);
    *(uint2*)(hi + e) = make_uint2(h0, h1);
    *(uint2*)(lo + e) = make_uint2(l0, l1);
}

__global__ void cvt_x_kernel(const float* __restrict__ src, int n4) {
    int i = blockIdx.x * blockDim.x + threadIdx.x;
    if (i >= n4) return;
    cvt_store4(((const float4*)src)[i], g_xhi, g_xlo, (size_t)i * 4);
}

__global__ void cvt_w_kernel(const float* __restrict__ Wqk, const float* __restrict__ Wv,
                             const float* __restrict__ Wproj) {
    int i = blockIdx.x * blockDim.x + threadIdx.x;   // float4 index
    if (i < 49152) {
        size_t e = (size_t)i * 4;
        const float* s = (e < 512u*256u) ? (Wqk + e) : (Wv + e - 512u*256u);
        cvt_store4(*(const float4*)s, g_whi, g_wlo, e);
    } else if (i < 49152 + 16384) {
        size_t e = (size_t)(i - 49152) * 4;
        cvt_store4(((const float4*)Wproj)[i - 49152], g_pwhi, g_pwlo, e);
    }
}

// =====================================================================
// positional softmax -> full gate-scaled bf16 hi/lo tensor [h][304][320]
// =====================================================================
__global__ void pos_kernel(const float* __restrict__ Wpos,
                           const float* __restrict__ bpos,
                           const float* __restrict__ gating)
{
    int row  = blockIdx.x * 4 + (threadIdx.x >> 5);   // h*304 + n
    int lane = threadIdx.x & 31;
    if (row >= Hh * 304) return;
    int h = row / 304, n = row % 304;
    __nv_bfloat16* dh = g_posbhi + (size_t)row * 320;
    __nv_bfloat16* dl = g_posblo + (size_t)row * 320;

    if (n >= Nn) {
        for (int t = 0; t < 10; t++) {
            dh[t*32 + lane] = __float2bfloat16(0.f);
            dl[t*32 + lane] = __float2bfloat16(0.f);
        }
        return;
    }
    float w0 = Wpos[h*3+0], w2 = Wpos[h*3+2], b = bpos[h];
    float s[10], mx = -1e30f;
    #pragma unroll
    for (int t = 0; t < 10; t++) {
        int m = t*32 + lane;
        float v = -1e30f;
        if (m < Nn) { float d = (float)(m - n); v = fmaf(w2*d, d, fmaf(w0, d, b)); }
        s[t] = v; mx = fmaxf(mx, v);
    }
    #pragma unroll
    for (int o = 16; o; o >>= 1) mx = fmaxf(mx, __shfl_xor_sync(0xffffffffu, mx, o));
    float esum = 0.f;
    #pragma unroll
    for (int t = 0; t < 10; t++) { s[t] = __expf(s[t] - mx); esum += s[t]; }
    #pragma unroll
    for (int o = 16; o; o >>= 1) esum += __shfl_xor_sync(0xffffffffu, esum, o);
    float g = 1.0f / (1.0f + __expf(-gating[h]));
    float inv = g / esum;
    #pragma unroll
    for (int t = 0; t < 10; t++) {
        int m = t*32 + lane;
        float v = (m < Nn) ? s[t] * inv : 0.f;
        __nv_bfloat16 hb = __float2bfloat16(v);
        __nv_bfloat16 lb = __float2bfloat16(v - __bfloat162float(hb));
        dh[m] = hb; dl[m] = lb;
    }
}

// =====================================================================
// mma.sync GEMM (R15 measured-best): cp.async 2-stage, 256 thr, 64x32/warp
// =====================================================================
#define PAD 40
#define TILE_CHUNK_B (128 * PAD * 2)
#define GEMM_CHUNK_B (4 * TILE_CHUNK_B)
#define GEMM_SMEM    (2 * GEMM_CHUNK_B)

__device__ __forceinline__ void gemm_stage(uint32_t sb, int buf,
                                           const __nv_bfloat16* s0,
                                           const __nv_bfloat16* s1,
                                           const __nv_bfloat16* s2,
                                           const __nv_bfloat16* s3,
                                           int k0, int tid)
{
    int r = tid >> 2, u = tid & 3;
    uint32_t base = sb + buf * GEMM_CHUNK_B + r * 80 + u * 16;
    size_t goff = (size_t)r * 256 + k0 + u * 8;
    CP_ASYNC16(base + 0*TILE_CHUNK_B,        s0 + goff);
    CP_ASYNC16(base + 0*TILE_CHUNK_B + 5120, s0 + goff + 64*256);
    CP_ASYNC16(base + 1*TILE_CHUNK_B,        s1 + goff);
    CP_ASYNC16(base + 1*TILE_CHUNK_B + 5120, s1 + goff + 64*256);
    CP_ASYNC16(base + 2*TILE_CHUNK_B,        s2 + goff);
    CP_ASYNC16(base + 2*TILE_CHUNK_B + 5120, s2 + goff + 64*256);
    CP_ASYNC16(base + 3*TILE_CHUNK_B,        s3 + goff);
    CP_ASYNC16(base + 3*TILE_CHUNK_B + 5120, s3 + goff + 64*256);
    CP_COMMIT();
}

__global__ __launch_bounds__(256, 2)
void tc_gemm(const float* __restrict__ bias, float* __restrict__ out, int mode)
{
    extern __shared__ __align__(16) char gsm[];
    uint32_t sb = (uint32_t)__cvta_generic_to_shared(gsm);

    int tid = threadIdx.x, wid = tid >> 5, lane = tid & 31;
    int row0 = blockIdx.y * 128;
    int col0 = blockIdx.x * 128;
    int warpM = wid & 1;
    int warpN = wid >> 1;
    int g  = lane >> 2;
    int tg = lane & 3;

    const __nv_bfloat16 *s0, *s1, *s2, *s3;
    if (mode == 0) {
        s0 = g_xhi + (size_t)row0 * 256;  s1 = g_xlo + (size_t)row0 * 256;
        s2 = g_whi + (size_t)col0 * 256;  s3 = g_wlo + (size_t)col0 * 256;
    } else {
        s0 = g_ohhi + (size_t)row0 * 256; s1 = g_ohlo + (size_t)row0 * 256;
        s2 = g_pwhi + (size_t)col0 * 256; s3 = g_pwlo + (size_t)col0 * 256;
    }

    float acc[4][4][4];
    #pragma unroll
    for (int mt = 0; mt < 4; mt++)
        #pragma unroll
        for (int nt = 0; nt < 4; nt++)
            #pragma unroll
            for (int f = 0; f < 4; f++) acc[mt][nt][f] = 0.f;

    gemm_stage(sb, 0, s0, s1, s2, s3, 0,  tid);
    gemm_stage(sb, 1, s0, s1, s2, s3, 32, tid);

    for (int kc = 0; kc < 8; kc++) {
        if (kc < 7) CP_WAIT1(); else CP_WAIT0();
        __syncthreads();

        const char* cbase = gsm + (kc & 1) * GEMM_CHUNK_B;
        #pragma unroll
        for (int kg = 0; kg < 2; kg++) {
            int kb = kg * 16 + tg * 2;
            uint32_t Ah[4][4], Al[4][4];
            #pragma unroll
            for (int mt = 0; mt < 4; mt++) {
                const char* pa = cbase + 0*TILE_CHUNK_B +
                                 (warpM*64 + mt*16 + g) * (PAD*2) + kb * 2;
                const char* pl = cbase + 1*TILE_CHUNK_B +
                                 (warpM*64 + mt*16 + g) * (PAD*2) + kb * 2;
                Ah[mt][0] = *(const uint32_t*)(pa);
                Ah[mt][1] = *(const uint32_t*)(pa + 8 * (PAD*2));
                Ah[mt][2] = *(const uint32_t*)(pa + 16);
                Ah[mt][3] = *(const uint32_t*)(pa + 8 * (PAD*2) + 16);
                Al[mt][0] = *(const uint32_t*)(pl);
                Al[mt][1] = *(const uint32_t*)(pl + 8 * (PAD*2));
                Al[mt][2] = *(const uint32_t*)(pl + 16);
                Al[mt][3] = *(const uint32_t*)(pl + 8 * (PAD*2) + 16);
            }
            uint32_t Bh[4][2], Bl[4][2];
            #pragma unroll
            for (int nt = 0; nt < 4; nt++) {
                const char* pb = cbase + 2*TILE_CHUNK_B +
                                 (warpN*32 + nt*8 + g) * (PAD*2) + kb * 2;
                const char* pbl = cbase + 3*TILE_CHUNK_B +
                                 (warpN*32 + nt*8 + g) * (PAD*2) + kb * 2;
                Bh[nt][0] = *(const uint32_t*)(pb);
                Bh[nt][1] = *(const uint32_t*)(pb + 16);
                Bl[nt][0] = *(const uint32_t*)(pbl);
                Bl[nt][1] = *(const uint32_t*)(pbl + 16);
            }
            #pragma unroll
            for (int mt = 0; mt < 4; mt++)
                #pragma unroll
                for (int nt = 0; nt < 4; nt++) {
                    mma16816(acc[mt][nt], Ah[mt], Bh[nt]);
                    mma16816(acc[mt][nt], Al[mt], Bh[nt]);
                    mma16816(acc[mt][nt], Ah[mt], Bl[nt]);
                }
        }

        if (kc < 6) {
            __syncthreads();
            gemm_stage(sb, kc & 1, s0, s1, s2, s3, (kc + 2) * 32, tid);
        }
    }

    int sec = col0 >> 8;
    int h   = ((col0 & 255) >> 5) + warpN;
    #pragma unroll
    for (int mt = 0; mt < 4; mt++) {
        #pragma unroll
        for (int rr = 0; rr < 2; rr++) {
            int r = row0 + warpM*64 + mt*16 + (lane >> 2) + rr*8;
            int bidx = r / Nn, n = r % Nn;
            #pragma unroll
            for (int nt = 0; nt < 4; nt++) {
                int col = col0 + warpN*32 + nt*8 + (lane & 3)*2;
                float d0 = acc[mt][nt][rr*2 + 0];
                float d1 = acc[mt][nt][rr*2 + 1];
                if (mode == 0) {
                    float* basep = (sec == 0) ? g_q : (sec == 1) ? g_k : g_v;
                    int d = col & 31;
                    *(float2*)(basep + (((size_t)bidx*Hh + h)*Nn + n)*HD + d) =
                        make_float2(d0, d1);
                } else {
                    *(float2*)(out + (size_t)r * 256 + col) =
                        make_float2(d0 + bias[col], d1 + bias[col + 1]);
                }
            }
        }
    }
}

// =====================================================================
// Flash-style mma attention v2: FULL K (hi/lo) + V^T (hi/lo) staged once
// in 91KB smem (2 CTAs/SM), ONE barrier, then 3 passes x 5 key blocks
// of pure mma with zero restaging / zero block barriers.
// =====================================================================
#define PADK 40
#define PADVF 328
#define NKB 5
#define AKB  (320*PADK*2)                 // 25600 B, one K tile (hi or lo)
#define AVB  (32*PADVF*2)                 // 20992 B, one V^T tile
#define ATTN_SMEM (2*AKB + 2*AVB)         // 93184 B

__global__ __launch_bounds__(256, 2)
void attn_mma(const float* __restrict__ gating)
{
    extern __shared__ __align__(16) char asm_[];
    __nv_bfloat16* kbhi = (__nv_bfloat16*)(asm_);
    __nv_bfloat16* kblo = (__nv_bfloat16*)(asm_ + AKB);
    __nv_bfloat16* vthi = (__nv_bfloat16*)(asm_ + 2*AKB);
    __nv_bfloat16* vtlo = (__nv_bfloat16*)(asm_ + 2*AKB + AVB);

    int bh = blockIdx.x, h = bh & 7, bidx = bh >> 3;
    int tid = threadIdx.x, wid = tid >> 5, lane = tid & 31;
    int g = lane >> 2, tg = lane & 3;

    const float* qg = g_q + (size_t)bh * Nn * HD;
    const float* kg = g_k + (size_t)bh * Nn * HD;
    const float* vg = g_v + (size_t)bh * Nn * HD;
    float gt = 1.0f / (1.0f + __expf(-gating[h]));
    float onemg = 1.0f - gt;
    const __nv_bfloat16* pbh = g_posbhi + (size_t)h * 304 * 320;
    const __nv_bfloat16* pbl = g_posblo + (size_t)h * 304 * 320;
    const float scale = 0.17677669529663687f;   // 1/sqrt(32)

    // ---- stage FULL K (hi/lo) and V^T (hi/lo) once ----
    {
        int sr = tid >> 2, sc8 = (tid & 3) * 8;
        #pragma unroll
        for (int it = 0; it < 5; it++) {
            int m = it*64 + sr;
            float4 f0, f1;
            if (m < Nn) {
                f0 = *(const float4*)(kg + (size_t)m*32 + sc8);
                f1 = *(const float4*)(kg + (size_t)m*32 + sc8 + 4);
            } else { f0 = make_float4(0,0,0,0); f1 = f0; }
            uint32_t h0,l0,h1,l1,h2,l2,h3,l3;
            bfsplit(h0,l0,f0.x,f0.y); bfsplit(h1,l1,f0.z,f0.w);
            bfsplit(h2,l2,f1.x,f1.y); bfsplit(h3,l3,f1.z,f1.w);
            *(uint4*)(kbhi + m*PADK + sc8) = make_uint4(h0,h1,h2,h3);
            *(uint4*)(kblo + m*PADK + sc8) = make_uint4(l0,l1,l2,l3);

            if (m < Nn) {
                f0 = *(const float4*)(vg + (size_t)m*32 + sc8);
                f1 = *(const float4*)(vg + (size_t)m*32 + sc8 + 4);
            } else { f0 = make_float4(0,0,0,0); f1 = f0; }
            float vv[8] = {f0.x,f0.y,f0.z,f0.w,f1.x,f1.y,f1.z,f1.w};
            #pragma unroll
            for (int j = 0; j < 8; j++) {
                __nv_bfloat16 hb = __float2bfloat16(vv[j]);
                __nv_bfloat16 lb = __float2bfloat16(vv[j] - __bfloat162float(hb));
                vthi[(sc8+j)*PADVF + m] = hb;
                vtlo[(sc8+j)*PADVF + m] = lb;
            }
        }
    }
    __syncthreads();

    for (int pass = 0; pass < 3; pass++) {
        int n0 = pass*128 + wid*16;
        if (n0 >= Nn) continue;
        int rg  = n0 + g;     if (rg  > Nn-1) rg  = Nn-1;
        int rg8 = n0 + g + 8; if (rg8 > Nn-1) rg8 = Nn-1;

        // Q A-frags (hi/lo), scale folded
        uint32_t qhi[2][4], qlo[2][4];
        #pragma unroll
        for (int ks = 0; ks < 2; ks++) {
            float2 f;
            f = *(const float2*)(qg + rg *32 + ks*16 + 2*tg);
            bfsplit(qhi[ks][0], qlo[ks][0], f.x*scale, f.y*scale);
            f = *(const float2*)(qg + rg8*32 + ks*16 + 2*tg);
            bfsplit(qhi[ks][1], qlo[ks][1], f.x*scale, f.y*scale);
            f = *(const float2*)(qg + rg *32 + ks*16 + 2*tg + 8);
            bfsplit(qhi[ks][2], qlo[ks][2], f.x*scale, f.y*scale);
            f = *(const float2*)(qg + rg8*32 + ks*16 + 2*tg + 8);
            bfsplit(qhi[ks][3], qlo[ks][3], f.x*scale, f.y*scale);
        }

        float O1[4][4], O2[4][4];
        #pragma unroll
        for (int dt = 0; dt < 4; dt++)
            #pragma unroll
            for (int f = 0; f < 4; f++) { O1[dt][f] = 0.f; O2[dt][f] = 0.f; }
        float mrun0 = -1e30f, mrun1 = -1e30f, lrun0 = 0.f, lrun1 = 0.f;

        for (int blk = 0; blk < NKB; blk++) {
            // ---- QK: S[nt][4] over 8 n8-tiles ----
            float S[8][4];
            #pragma unroll
            for (int nt = 0; nt < 8; nt++)
                #pragma unroll
                for (int f = 0; f < 4; f++) S[nt][f] = 0.f;
            #pragma unroll
            for (int nt = 0; nt < 8; nt++) {
                #pragma unroll
                for (int ks = 0; ks < 2; ks++) {
                    const char* pb  = (const char*)kbhi +
                        ((blk*64 + nt*8 + g)*PADK + ks*16 + tg*2) * 2;
                    const char* pbl2 = (const char*)kblo +
                        ((blk*64 + nt*8 + g)*PADK + ks*16 + tg*2) * 2;
                    uint32_t Bh[2] = { *(const uint32_t*)pb,
                                       *(const uint32_t*)(pb + 16) };
                    uint32_t Bl[2] = { *(const uint32_t*)pbl2,
                                       *(const uint32_t*)(pbl2 + 16) };
                    mma16816(S[nt], qhi[ks], Bh);
                    mma16816(S[nt], qlo[ks], Bh);
                    mma16816(S[nt], qhi[ks], Bl);
                }
            }
            // mask padded keys (K rows >=300 are zeros; must be -inf)
            if (blk == NKB-1) {
                #pragma unroll
                for (int nt = 0; nt < 8; nt++) {
                    int key = blk*64 + nt*8 + 2*tg;
                    if (key   >= Nn) { S[nt][0] = -1e30f; S[nt][2] = -1e30f; }
                    if (key+1 >= Nn) { S[nt][1] = -1e30f; S[nt][3] = -1e30f; }
                }
            }
            // ---- online softmax ----
            float bm0 = -1e30f, bm1 = -1e30f;
            #pragma unroll
            for (int nt = 0; nt < 8; nt++) {
                bm0 = fmaxf(bm0, fmaxf(S[nt][0], S[nt][1]));
                bm1 = fmaxf(bm1, fmaxf(S[nt][2], S[nt][3]));
            }
            bm0 = fmaxf(bm0, __shfl_xor_sync(0xffffffffu, bm0, 1));
            bm0 = fmaxf(bm0, __shfl_xor_sync(0xffffffffu, bm0, 2));
            bm1 = fmaxf(bm1, __shfl_xor_sync(0xffffffffu, bm1, 1));
            bm1 = fmaxf(bm1, __shfl_xor_sync(0xffffffffu, bm1, 2));
            float mn0 = fmaxf(mrun0, bm0), mn1 = fmaxf(mrun1, bm1);
            float fc0 = __expf(mrun0 - mn0), fc1 = __expf(mrun1 - mn1);
            mrun0 = mn0; mrun1 = mn1;
            float ls0 = 0.f, ls1 = 0.f;
            #pragma unroll
            for (int nt = 0; nt < 8; nt++) {
                S[nt][0] = __expf(S[nt][0] - mn0); ls0 += S[nt][0];
                S[nt][1] = __expf(S[nt][1] - mn0); ls0 += S[nt][1];
                S[nt][2] = __expf(S[nt][2] - mn1); ls1 += S[nt][2];
                S[nt][3] = __expf(S[nt][3] - mn1); ls1 += S[nt][3];
            }
            ls0 += __shfl_xor_sync(0xffffffffu, ls0, 1);
            ls0 += __shfl_xor_sync(0xffffffffu, ls0, 2);
            ls1 += __shfl_xor_sync(0xffffffffu, ls1, 1);
            ls1 += __shfl_xor_sync(0xffffffffu, ls1, 2);
            lrun0 = lrun0*fc0 + ls0;
            lrun1 = lrun1*fc1 + ls1;
            #pragma unroll
            for (int dt = 0; dt < 4; dt++) {
                O1[dt][0] *= fc0; O1[dt][1] *= fc0;
                O1[dt][2] *= fc1; O1[dt][3] *= fc1;
            }
            // ---- AV (soft + pos) over 4 k16 steps ----
            #pragma unroll
            for (int j = 0; j < 4; j++) {
                uint32_t phi[4], plo[4];
                bfsplit(phi[0], plo[0], S[2*j][0],   S[2*j][1]);
                bfsplit(phi[1], plo[1], S[2*j][2],   S[2*j][3]);
                bfsplit(phi[2], plo[2], S[2*j+1][0], S[2*j+1][1]);
                bfsplit(phi[3], plo[3], S[2*j+1][2], S[2*j+1][3]);
                int keyb = blk*64 + j*16 + 2*tg;
                uint32_t pph[4], ppl[4];
                pph[0] = *(const uint32_t*)(pbh + (size_t)(n0+g  )*320 + keyb);
                pph[1] = *(const uint32_t*)(pbh + (size_t)(n0+g+8)*320 + keyb);
                pph[2] = *(const uint32_t*)(pbh + (size_t)(n0+g  )*320 + keyb + 8);
                pph[3] = *(const uint32_t*)(pbh + (size_t)(n0+g+8)*320 + keyb + 8);
                ppl[0] = *(const uint32_t*)(pbl + (size_t)(n0+g  )*320 + keyb);
                ppl[1] = *(const uint32_t*)(pbl + (size_t)(n0+g+8)*320 + keyb);
                ppl[2] = *(const uint32_t*)(pbl + (size_t)(n0+g  )*320 + keyb + 8);
                ppl[3] = *(const uint32_t*)(pbl + (size_t)(n0+g+8)*320 + keyb + 8);
                #pragma unroll
                for (int dt = 0; dt < 4; dt++) {
                    const char* pv = (const char*)vthi +
                        ((dt*8 + g)*PADVF + blk*64 + j*16 + tg*2) * 2;
                    const char* pvl = (const char*)vtlo +
                        ((dt*8 + g)*PADVF + blk*64 + j*16 + tg*2) * 2;
                    uint32_t Vh[2] = { *(const uint32_t*)pv,
                                       *(const uint32_t*)(pv + 16) };
                    uint32_t Vl[2] = { *(const uint32_t*)pvl,
                                       *(const uint32_t*)(pvl + 16) };
                    mma16816(O1[dt], phi, Vh);
                    mma16816(O1[dt], plo, Vh);
                    mma16816(O1[dt], phi, Vl);
                    mma16816(O2[dt], pph, Vh);
                    mma16816(O2[dt], ppl, Vh);
                    mma16816(O2[dt], pph, Vl);
                }
            }
        }

        // ---- epilogue: out = (1-g)/l * O1 + O2, write bf16 hi/lo ----
        float r0 = onemg / lrun0, r1 = onemg / lrun1;
        #pragma unroll
        for (int dt = 0; dt < 4; dt++) {
            int d = dt*8 + tg*2;
            if (n0 + g < Nn) {
                float v0 = fmaf(O1[dt][0], r0, O2[dt][0]);
                float v1 = fmaf(O1[dt][1], r0, O2[dt][1]);
                uint32_t hb, lb; bfsplit(hb, lb, v0, v1);
                size_t e = ((size_t)bidx*Nn + n0+g)*Cc + h*HD + d;
                *(uint32_t*)(g_ohhi + e) = hb;
                *(uint32_t*)(g_ohlo + e) = lb;
            }
            if (n0 + g + 8 < Nn) {
                float v0 = fmaf(O1[dt][2], r1, O2[dt][2]);
                float v1 = fmaf(O1[dt][3], r1, O2[dt][3]);
                uint32_t hb, lb; bfsplit(hb, lb, v0, v1);
                size_t e = ((size_t)bidx*Nn + n0+g+8)*Cc + h*HD + d;
                *(uint32_t*)(g_ohhi + e) = hb;
                *(uint32_t*)(g_ohlo + e) = lb;
            }
        }
    }
}

// =====================================================================
extern "C" void kernel_launch(void* const* d_in, const int* in_sizes, int n_in,
                              void* d_out, int out_size)
{
    const float* x      = (const float*)d_in[0];
    const float* Wqk    = (const float*)d_in[1];
    const float* Wv     = (const float*)d_in[2];
    const float* Wpos   = (const float*)d_in[3];
    const float* bpos   = (const float*)d_in[4];
    const float* Wproj  = (const float*)d_in[5];
    const float* bproj  = (const float*)d_in[6];
    const float* gating = (const float*)d_in[7];
    float* out = (float*)d_out;

    cudaFuncSetAttribute(tc_gemm, cudaFuncAttributeMaxDynamicSharedMemorySize,
                         GEMM_SMEM);
    cudaFuncSetAttribute(attn_mma, cudaFuncAttributeMaxDynamicSharedMemorySize,
                         ATTN_SMEM);

    // 0) bf16 hi/lo conversions
    int n4x = ROWS * Cc / 4;
    cvt_x_kernel<<<(n4x + 255) / 256, 256>>>(x, n4x);
    cvt_w_kernel<<<(49152 + 16384 + 255) / 256, 256>>>(Wqk, Wv, Wproj);

    // 1) gate-scaled positional softmax tensor (bf16 hi/lo)
    pos_kernel<<<(Hh*304 + 3) / 4, 128>>>(Wpos, bpos, gating);

    // 2) QKV projection on tensor cores
    dim3 g1(6, ROWS / 128);
    tc_gemm<<<g1, 256, GEMM_SMEM>>>(nullptr, nullptr, 0);

    // 3) flash-style mma attention, one CTA per (b,h)
    attn_mma<<<BH, 256, ATTN_SMEM>>>(gating);

    // 4) output projection on tensor cores + bias
    dim3 g2(2, ROWS / 128);
    tc_gemm<<<g2, 256, GEMM_SMEM>>>(bproj, out, 1);
}